// round 6
// baseline (speedup 1.0000x reference)
#include <cuda_runtime.h>
#include <cstdint>

// ---------------------------------------------------------------------------
// LongformerAttention  B=2, S=4096, HID=1024, H=16, D=64, W=64
// Round 6: mma.sync tf32 GEMMs with 64x64 warp tiles (1.0 LDS/MMA) +
// fragment double-buffering. Block 128x256, 1 block/SM, cp.async 2-stage.
// (tcgen05 rejected by harness ptxas target sm_103 — not available.)
// ---------------------------------------------------------------------------

#define S_LEN   4096
#define HIDDEN  1024
#define NHEAD   16
#define HDIM    64
#define NCHUNK  64
#define BATCH   2
#define MROWS   (BATCH * S_LEN)   // 8192

__device__ float g_Q[(size_t)MROWS * HIDDEN];
__device__ float g_K[(size_t)MROWS * HIDDEN];
__device__ float g_V[(size_t)MROWS * HIDDEN];
__device__ float g_ctx[(size_t)MROWS * HIDDEN];
__device__ float g_Xr[(size_t)MROWS * HIDDEN];          // tf32-rounded X
__device__ float g_Wr[4][(size_t)HIDDEN * HIDDEN];      // tf32-rounded weights

__device__ __forceinline__ float to_tf32(float x) {
    float y;
    asm("cvt.rna.tf32.f32 %0, %1;" : "=f"(y) : "f"(x));
    return y;
}

__device__ __forceinline__ void mma_tf32(float c[4], const uint32_t a[4], const uint32_t b[2]) {
    asm volatile(
        "mma.sync.aligned.m16n8k8.row.col.f32.tf32.tf32.f32 "
        "{%0,%1,%2,%3}, {%4,%5,%6,%7}, {%8,%9}, {%0,%1,%2,%3};"
        : "+f"(c[0]), "+f"(c[1]), "+f"(c[2]), "+f"(c[3])
        : "r"(a[0]), "r"(a[1]), "r"(a[2]), "r"(a[3]), "r"(b[0]), "r"(b[1]));
}

__device__ __forceinline__ void cp_async16(uint32_t dst, const void* src) {
    asm volatile("cp.async.cg.shared.global [%0], [%1], 16;\n"
                 :: "r"(dst), "l"(src));
}

// ---------------------------------------------------------------------------
// tf32 pre-rounding pass
// ---------------------------------------------------------------------------
__global__ __launch_bounds__(256) void round_tf32_kernel(
    const float* __restrict__ in, float* __restrict__ out, int n4)
{
    int i = blockIdx.x * blockDim.x + threadIdx.x;
    if (i < n4) {
        float4 v = ((const float4*)in)[i];
        v.x = to_tf32(v.x); v.y = to_tf32(v.y);
        v.z = to_tf32(v.z); v.w = to_tf32(v.w);
        ((float4*)out)[i] = v;
    }
}

// ---------------------------------------------------------------------------
// Pipelined tf32 GEMM: C[M,N] = A[M,K] @ B[K,N] + bias[N]
// Block tile 128x256, BK=32, 2-stage cp.async double buffer.
// 256 threads (8 warps, 2x4), warp tile 64x64 -> 1.0 LDS per MMA.
// As[m][k] stride 36, Bs[k][n] stride 264 (both conflict-free for frag loads).
// A and B must be tf32-pre-rounded.
// ---------------------------------------------------------------------------
#define GK 1024
#define GN 1024
#define AS_STRIDE 36
#define BS_STRIDE 264
#define AS_SIZE (128 * AS_STRIDE)   // 4608 floats
#define BS_SIZE (32 * BS_STRIDE)    // 8448 floats
#define GEMM_SMEM_BYTES (2 * (AS_SIZE + BS_SIZE) * (int)sizeof(float))  // 104448

__device__ __forceinline__ void gemm_body_pipe(
    const float* __restrict__ A, const float* __restrict__ Bm,
    const float* __restrict__ bias, float* __restrict__ C, float* sm)
{
    float* As0 = sm;                       // 2 x 4608
    float* Bs0 = sm + 2 * AS_SIZE;         // 2 x 8448

    const int tid  = threadIdx.x;
    const int lane = tid & 31;
    const int wid  = tid >> 5;
    const int wm   = wid >> 2;             // 0..1 (64 rows each)
    const int wn   = wid & 3;              // 0..3 (64 cols each)
    const int qq   = lane >> 2;            // 0..7
    const int qk   = lane & 3;             // 0..3
    const int brow = blockIdx.y * 128;
    const int bcol = blockIdx.x * 256;

    const int la_r  = tid >> 3;            // 0..31 (+32*i)
    const int la_c4 = (tid & 7) << 2;      // 0..28
    const int lb_n4 = (tid & 63) << 2;     // 0..252

    float acc[4][8][4];
#pragma unroll
    for (int i = 0; i < 4; i++)
#pragma unroll
        for (int j = 0; j < 8; j++)
#pragma unroll
            for (int t = 0; t < 4; t++) acc[i][j][t] = 0.f;

    auto issue = [&](int buf, int k0) {
        float* Asb = As0 + buf * AS_SIZE;
        float* Bsb = Bs0 + buf * BS_SIZE;
#pragma unroll
        for (int i = 0; i < 4; i++) {
            int r = la_r + i * 32;
            uint32_t dst = (uint32_t)__cvta_generic_to_shared(Asb + r * AS_STRIDE + la_c4);
            cp_async16(dst, A + (size_t)(brow + r) * GK + k0 + la_c4);
        }
#pragma unroll
        for (int i = 0; i < 8; i++) {
            int idx = tid + i * 256;
            int kr = idx >> 6;             // 0..31
            uint32_t dst = (uint32_t)__cvta_generic_to_shared(Bsb + kr * BS_STRIDE + lb_n4);
            cp_async16(dst, Bm + (size_t)(k0 + kr) * GN + bcol + lb_n4);
        }
        asm volatile("cp.async.commit_group;\n" ::: "memory");
    };

    issue(0, 0);

    // fragment double buffers
    uint32_t afr[2][4][4];
    uint32_t bfr[2][8][2];

    auto load_frag = [&](const float* Asb, const float* Bsb, int pb, int ks) {
        const int kb = ks * 8;
#pragma unroll
        for (int mt = 0; mt < 4; mt++) {
            int r0 = wm * 64 + mt * 16 + qq;
            afr[pb][mt][0] = __float_as_uint(Asb[r0 * AS_STRIDE + kb + qk]);
            afr[pb][mt][1] = __float_as_uint(Asb[(r0 + 8) * AS_STRIDE + kb + qk]);
            afr[pb][mt][2] = __float_as_uint(Asb[r0 * AS_STRIDE + kb + qk + 4]);
            afr[pb][mt][3] = __float_as_uint(Asb[(r0 + 8) * AS_STRIDE + kb + qk + 4]);
        }
#pragma unroll
        for (int nt = 0; nt < 8; nt++) {
            int cN = wn * 64 + nt * 8 + qq;
            bfr[pb][nt][0] = __float_as_uint(Bsb[(kb + qk) * BS_STRIDE + cN]);
            bfr[pb][nt][1] = __float_as_uint(Bsb[(kb + qk + 4) * BS_STRIDE + cN]);
        }
    };

    for (int k0 = 0; k0 < GK; k0 += 32) {
        const int buf = (k0 >> 5) & 1;
        if (k0 + 32 < GK) {
            issue(buf ^ 1, k0 + 32);
            asm volatile("cp.async.wait_group 1;\n" ::: "memory");
        } else {
            asm volatile("cp.async.wait_group 0;\n" ::: "memory");
        }
        __syncthreads();

        const float* Asb = As0 + buf * AS_SIZE;
        const float* Bsb = Bs0 + buf * BS_SIZE;

        load_frag(Asb, Bsb, 0, 0);
#pragma unroll
        for (int ks = 0; ks < 4; ks++) {
            const int cur = ks & 1;
            if (ks < 3)
                load_frag(Asb, Bsb, cur ^ 1, ks + 1);
#pragma unroll
            for (int mt = 0; mt < 4; mt++)
#pragma unroll
                for (int nt = 0; nt < 8; nt++)
                    mma_tf32(acc[mt][nt], afr[cur][mt], bfr[cur][nt]);
        }
        __syncthreads();
    }

    // epilogue
#pragma unroll
    for (int nt = 0; nt < 8; nt++) {
        int cc = bcol + wn * 64 + nt * 8 + 2 * qk;
        float2 bv = *(const float2*)(bias + cc);
#pragma unroll
        for (int mt = 0; mt < 4; mt++) {
            int r = brow + wm * 64 + mt * 16 + qq;
            float2 o0 = make_float2(acc[mt][nt][0] + bv.x, acc[mt][nt][1] + bv.y);
            float2 o1 = make_float2(acc[mt][nt][2] + bv.x, acc[mt][nt][3] + bv.y);
            *(float2*)(C + (size_t)r * GN + cc) = o0;
            *(float2*)(C + (size_t)(r + 8) * GN + cc) = o1;
        }
    }
}

__global__ __launch_bounds__(256, 1) void gemm_qkv_kernel(
    const float* __restrict__ X, const float* __restrict__ Wr4,
    const float* __restrict__ bq, const float* __restrict__ bk,
    const float* __restrict__ bv,
    float* __restrict__ Q, float* __restrict__ K, float* __restrict__ V)
{
    extern __shared__ float smg[];
    const float* W = Wr4 + (size_t)blockIdx.z * HIDDEN * HIDDEN;
    const float* b = (blockIdx.z == 0) ? bq : (blockIdx.z == 1) ? bk : bv;
    float*       C = (blockIdx.z == 0) ? Q  : (blockIdx.z == 1) ? K  : V;
    gemm_body_pipe(X, W, b, C, smg);
}

__global__ __launch_bounds__(256, 1) void gemm_o_kernel(
    const float* __restrict__ A, const float* __restrict__ W,
    const float* __restrict__ b, float* __restrict__ C)
{
    extern __shared__ float smg[];
    gemm_body_pipe(A, W, b, C, smg);
}

// ---------------------------------------------------------------------------
// Banded attention (unchanged from R4 — mma.sync tf32, hi/lo-compensated P)
// ---------------------------------------------------------------------------
#define PW  68
#define PPW 196
#define ATTN_SMEM_FLOATS (64*PW + 192*PW + 2*64*PPW + 192 + 256 + 256)

__global__ __launch_bounds__(256) void attn_kernel(const float* __restrict__ maskp)
{
    extern __shared__ float sm[];
    float* Qs   = sm;
    float* Ks   = Qs + 64 * PW;
    float* Ph   = Ks + 192 * PW;
    float* Pl   = Ph + 64 * PPW;
    float* vld  = Pl + 64 * PPW;
    float* redM = vld + 192;
    float* redS = redM + 256;

    const int c = blockIdx.x;
    const int h = blockIdx.y;
    const int b = blockIdx.z;
    const int tid  = threadIdx.x;
    const int lane = tid & 31;
    const int wid  = tid >> 5;
    const int wm   = wid >> 2;
    const int wn   = wid & 3;
    const int qq   = lane >> 2;
    const int qk   = lane & 3;

    const size_t headoff = (size_t)h * HDIM;
    const size_t bbase   = (size_t)b * S_LEN;
    const int base = c * 64 - 64;

#pragma unroll
    for (int it = 0; it < 4; it++) {
        int idx = tid + it * 256;
        int r  = idx >> 4;
        int c4 = (idx & 15) << 2;
        float4 v = *(const float4*)(g_Q + (bbase + c * 64 + r) * HIDDEN + headoff + c4);
        float* p = &Qs[r * PW + c4];
        p[0] = to_tf32(v.x); p[1] = to_tf32(v.y);
        p[2] = to_tf32(v.z); p[3] = to_tf32(v.w);
    }
#pragma unroll
    for (int it = 0; it < 12; it++) {
        int idx = tid + it * 256;
        int r  = idx >> 4;
        int c4 = (idx & 15) << 2;
        int jg = base + r;
        float4 kv = make_float4(0.f, 0.f, 0.f, 0.f);
        if (jg >= 0 && jg < S_LEN)
            kv = *(const float4*)(g_K + (bbase + jg) * HIDDEN + headoff + c4);
        float* p = &Ks[r * PW + c4];
        p[0] = to_tf32(kv.x); p[1] = to_tf32(kv.y);
        p[2] = to_tf32(kv.z); p[3] = to_tf32(kv.w);
    }
    if (tid < 192) {
        int jg = base + tid;
        vld[tid] = (jg >= 0 && jg < S_LEN && maskp[b * S_LEN + jg] > 0.f) ? 1.f : 0.f;
    }
    __syncthreads();

    float acc[2][6][4];
#pragma unroll
    for (int mt = 0; mt < 2; mt++)
#pragma unroll
        for (int nt = 0; nt < 6; nt++)
#pragma unroll
            for (int t = 0; t < 4; t++) acc[mt][nt][t] = 0.f;

#pragma unroll
    for (int ks = 0; ks < 8; ks++) {
        const int kb = ks * 8;
        uint32_t af[2][4];
#pragma unroll
        for (int mt = 0; mt < 2; mt++) {
            int r0 = wm * 32 + mt * 16 + qq;
            af[mt][0] = __float_as_uint(Qs[r0 * PW + kb + qk]);
            af[mt][1] = __float_as_uint(Qs[(r0 + 8) * PW + kb + qk]);
            af[mt][2] = __float_as_uint(Qs[r0 * PW + kb + qk + 4]);
            af[mt][3] = __float_as_uint(Qs[(r0 + 8) * PW + kb + qk + 4]);
        }
        uint32_t bf[6][2];
#pragma unroll
        for (int nt = 0; nt < 6; nt++) {
            int n = wn * 48 + nt * 8 + qq;
            bf[nt][0] = __float_as_uint(Ks[n * PW + kb + qk]);
            bf[nt][1] = __float_as_uint(Ks[n * PW + kb + qk + 4]);
        }
#pragma unroll
        for (int mt = 0; mt < 2; mt++)
#pragma unroll
            for (int nt = 0; nt < 6; nt++)
                mma_tf32(acc[mt][nt], af[mt], bf[nt]);
    }

    float mrow[2][2];
#pragma unroll
    for (int mt = 0; mt < 2; mt++)
#pragma unroll
        for (int hf = 0; hf < 2; hf++) mrow[mt][hf] = -1e30f;

#pragma unroll
    for (int mt = 0; mt < 2; mt++)
#pragma unroll
        for (int nt = 0; nt < 6; nt++) {
            int colb = wn * 48 + nt * 8 + 2 * qk;
#pragma unroll
            for (int hf = 0; hf < 2; hf++) {
                int row = wm * 32 + mt * 16 + qq + 8 * hf;
#pragma unroll
                for (int e = 0; e < 2; e++) {
                    int col = colb + e;
                    float v = acc[mt][nt][hf * 2 + e] * 0.125f;
                    bool ok = (col >= row) && (col <= row + 128) && (vld[col] > 0.f);
                    v = ok ? v : -1e9f;
                    acc[mt][nt][hf * 2 + e] = v;
                    mrow[mt][hf] = fmaxf(mrow[mt][hf], v);
                }
            }
        }
#pragma unroll
    for (int mt = 0; mt < 2; mt++)
#pragma unroll
        for (int hf = 0; hf < 2; hf++) {
            float m = mrow[mt][hf];
            m = fmaxf(m, __shfl_xor_sync(0xffffffffu, m, 1));
            m = fmaxf(m, __shfl_xor_sync(0xffffffffu, m, 2));
            mrow[mt][hf] = m;
        }
    if (qk == 0) {
#pragma unroll
        for (int mt = 0; mt < 2; mt++)
#pragma unroll
            for (int hf = 0; hf < 2; hf++)
                redM[wn * 64 + wm * 32 + mt * 16 + qq + 8 * hf] = mrow[mt][hf];
    }
    __syncthreads();

    float gmv[2][2], srow[2][2];
#pragma unroll
    for (int mt = 0; mt < 2; mt++)
#pragma unroll
        for (int hf = 0; hf < 2; hf++) {
            int row = wm * 32 + mt * 16 + qq + 8 * hf;
            float m = fmaxf(fmaxf(redM[row], redM[64 + row]),
                            fmaxf(redM[128 + row], redM[192 + row]));
            gmv[mt][hf] = m;
            srow[mt][hf] = 0.f;
        }

#pragma unroll
    for (int mt = 0; mt < 2; mt++)
#pragma unroll
        for (int nt = 0; nt < 6; nt++) {
            int colb = wn * 48 + nt * 8 + 2 * qk;
#pragma unroll
            for (int hf = 0; hf < 2; hf++) {
                int row = wm * 32 + mt * 16 + qq + 8 * hf;
                float p0 = __expf(acc[mt][nt][hf * 2 + 0] - gmv[mt][hf]);
                float p1 = __expf(acc[mt][nt][hf * 2 + 1] - gmv[mt][hf]);
                srow[mt][hf] += p0 + p1;
                float h0 = to_tf32(p0), h1 = to_tf32(p1);
                *(float2*)&Ph[row * PPW + colb] = make_float2(h0, h1);
                *(float2*)&Pl[row * PPW + colb] = make_float2(to_tf32(p0 - h0),
                                                             to_tf32(p1 - h1));
            }
        }

#pragma unroll
    for (int mt = 0; mt < 2; mt++)
#pragma unroll
        for (int hf = 0; hf < 2; hf++) {
            float s = srow[mt][hf];
            s += __shfl_xor_sync(0xffffffffu, s, 1);
            s += __shfl_xor_sync(0xffffffffu, s, 2);
            srow[mt][hf] = s;
        }
    if (qk == 0) {
#pragma unroll
        for (int mt = 0; mt < 2; mt++)
#pragma unroll
            for (int hf = 0; hf < 2; hf++)
                redS[wn * 64 + wm * 32 + mt * 16 + qq + 8 * hf] = srow[mt][hf];
    }

#pragma unroll
    for (int it = 0; it < 12; it++) {
        int idx = tid + it * 256;
        int r  = idx >> 4;
        int c4 = (idx & 15) << 2;
        int jg = base + r;
        float4 vv = make_float4(0.f, 0.f, 0.f, 0.f);
        if (jg >= 0 && jg < S_LEN)
            vv = *(const float4*)(g_V + (bbase + jg) * HIDDEN + headoff + c4);
        float* p = &Ks[r * PW + c4];
        p[0] = to_tf32(vv.x); p[1] = to_tf32(vv.y);
        p[2] = to_tf32(vv.z); p[3] = to_tf32(vv.w);
    }
    __syncthreads();

    float c2[2][2][4];
#pragma unroll
    for (int mt = 0; mt < 2; mt++)
#pragma unroll
        for (int nt = 0; nt < 2; nt++)
#pragma unroll
            for (int t = 0; t < 4; t++) c2[mt][nt][t] = 0.f;

#pragma unroll
    for (int ks = 0; ks < 24; ks++) {
        const int kb = ks * 8;
        uint32_t ah[2][4], al[2][4];
#pragma unroll
        for (int mt = 0; mt < 2; mt++) {
            int r0 = wm * 32 + mt * 16 + qq;
            ah[mt][0] = __float_as_uint(Ph[r0 * PPW + kb + qk]);
            ah[mt][1] = __float_as_uint(Ph[(r0 + 8) * PPW + kb + qk]);
            ah[mt][2] = __float_as_uint(Ph[r0 * PPW + kb + qk + 4]);
            ah[mt][3] = __float_as_uint(Ph[(r0 + 8) * PPW + kb + qk + 4]);
            al[mt][0] = __float_as_uint(Pl[r0 * PPW + kb + qk]);
            al[mt][1] = __float_as_uint(Pl[(r0 + 8) * PPW + kb + qk]);
            al[mt][2] = __float_as_uint(Pl[r0 * PPW + kb + qk + 4]);
            al[mt][3] = __float_as_uint(Pl[(r0 + 8) * PPW + kb + qk + 4]);
        }
        uint32_t bf[2][2];
#pragma unroll
        for (int nt = 0; nt < 2; nt++) {
            int n = wn * 16 + nt * 8 + qq;
            bf[nt][0] = __float_as_uint(Ks[(kb + qk) * PW + n]);
            bf[nt][1] = __float_as_uint(Ks[(kb + qk + 4) * PW + n]);
        }
#pragma unroll
        for (int mt = 0; mt < 2; mt++)
#pragma unroll
            for (int nt = 0; nt < 2; nt++) {
                mma_tf32(c2[mt][nt], ah[mt], bf[nt]);
                mma_tf32(c2[mt][nt], al[mt], bf[nt]);
            }
    }

#pragma unroll
    for (int mt = 0; mt < 2; mt++)
#pragma unroll
        for (int hf = 0; hf < 2; hf++) {
            int row = wm * 32 + mt * 16 + qq + 8 * hf;
            float s = redS[row] + redS[64 + row] + redS[128 + row] + redS[192 + row];
            float rinv = 1.f / s;
            float* Og = g_ctx + (bbase + c * 64 + row) * HIDDEN + headoff;
#pragma unroll
            for (int nt = 0; nt < 2; nt++) {
                int col = wn * 16 + nt * 8 + 2 * qk;
                *(float2*)(Og + col) = make_float2(
                    to_tf32(c2[mt][nt][hf * 2 + 0] * rinv),
                    to_tf32(c2[mt][nt][hf * 2 + 1] * rinv));
            }
        }
}

// ---------------------------------------------------------------------------
extern "C" void kernel_launch(void* const* d_in, const int* in_sizes, int n_in,
                              void* d_out, int out_size)
{
    const float* X    = (const float*)d_in[0];
    const float* mask = (const float*)d_in[1];
    const float* Wq   = (const float*)d_in[2];
    const float* bq   = (const float*)d_in[3];
    const float* Wk   = (const float*)d_in[4];
    const float* bk   = (const float*)d_in[5];
    const float* Wv   = (const float*)d_in[6];
    const float* bv   = (const float*)d_in[7];
    const float* Wo   = (const float*)d_in[8];
    const float* bo   = (const float*)d_in[9];
    float* out = (float*)d_out;

    float *qp, *kp, *vp, *cp, *xrp, *wrp;
    cudaGetSymbolAddress((void**)&qp, g_Q);
    cudaGetSymbolAddress((void**)&kp, g_K);
    cudaGetSymbolAddress((void**)&vp, g_V);
    cudaGetSymbolAddress((void**)&cp, g_ctx);
    cudaGetSymbolAddress((void**)&xrp, g_Xr);
    cudaGetSymbolAddress((void**)&wrp, g_Wr);
    float* wo_r = wrp + 3 * (size_t)HIDDEN * HIDDEN;

    const int attn_smem = ATTN_SMEM_FLOATS * (int)sizeof(float);
    cudaFuncSetAttribute(attn_kernel, cudaFuncAttributeMaxDynamicSharedMemorySize,
                         attn_smem);
    cudaFuncSetAttribute(gemm_qkv_kernel, cudaFuncAttributeMaxDynamicSharedMemorySize,
                         GEMM_SMEM_BYTES);
    cudaFuncSetAttribute(gemm_o_kernel, cudaFuncAttributeMaxDynamicSharedMemorySize,
                         GEMM_SMEM_BYTES);

    // ---- tf32 pre-rounding (X + 4 weights)
    const int xN4 = MROWS * HIDDEN / 4;
    const int wN4 = HIDDEN * HIDDEN / 4;
    round_tf32_kernel<<<(xN4 + 255) / 256, 256>>>(X, xrp, xN4);
    round_tf32_kernel<<<(wN4 + 255) / 256, 256>>>(Wq, wrp, wN4);
    round_tf32_kernel<<<(wN4 + 255) / 256, 256>>>(Wk, wrp + (size_t)HIDDEN * HIDDEN, wN4);
    round_tf32_kernel<<<(wN4 + 255) / 256, 256>>>(Wv, wrp + 2 * (size_t)HIDDEN * HIDDEN, wN4);
    round_tf32_kernel<<<(wN4 + 255) / 256, 256>>>(Wo, wo_r, wN4);

    dim3 gblk(256);
    dim3 gqkv(HIDDEN / 256, MROWS / 128, 3);       // 4 x 64 x 3
    gemm_qkv_kernel<<<gqkv, gblk, GEMM_SMEM_BYTES>>>(xrp, wrp, bq, bk, bv, qp, kp, vp);

    dim3 agrid(NCHUNK, NHEAD, BATCH);
    attn_kernel<<<agrid, gblk, attn_smem>>>(mask);

    dim3 go(HIDDEN / 256, MROWS / 128);            // 4 x 64
    gemm_o_kernel<<<go, gblk, GEMM_SMEM_BYTES>>>(cp, wo_r, bo, out);
}

// round 7
// speedup vs baseline: 1.0641x; 1.0641x over previous
#include <cuda_runtime.h>
#include <cstdint>

// ---------------------------------------------------------------------------
// LongformerAttention  B=2, S=4096, HID=1024, H=16, D=64, W=64
// Round 7: tf32 GEMMs with ldmatrix.x4 fragment loads (6 LDSM vs 24 LDS per
// warp-k8), n-major B (weights pre-transposed), 3-stage cp.async pipeline.
// Block 128x128, 2 blocks/SM. Attention unchanged.
// ---------------------------------------------------------------------------

#define S_LEN   4096
#define HIDDEN  1024
#define NHEAD   16
#define HDIM    64
#define NCHUNK  64
#define BATCH   2
#define MROWS   (BATCH * S_LEN)   // 8192

__device__ float g_Q[(size_t)MROWS * HIDDEN];
__device__ float g_K[(size_t)MROWS * HIDDEN];
__device__ float g_V[(size_t)MROWS * HIDDEN];
__device__ float g_ctx[(size_t)MROWS * HIDDEN];
__device__ float g_Xr[(size_t)MROWS * HIDDEN];          // tf32-rounded X
__device__ float g_Wt[4][(size_t)HIDDEN * HIDDEN];      // tf32-rounded, TRANSPOSED W [n][k]

__device__ __forceinline__ float to_tf32(float x) {
    float y;
    asm("cvt.rna.tf32.f32 %0, %1;" : "=f"(y) : "f"(x));
    return y;
}

__device__ __forceinline__ void mma_tf32(float c[4], const uint32_t a[4], const uint32_t b[2]) {
    asm volatile(
        "mma.sync.aligned.m16n8k8.row.col.f32.tf32.tf32.f32 "
        "{%0,%1,%2,%3}, {%4,%5,%6,%7}, {%8,%9}, {%0,%1,%2,%3};"
        : "+f"(c[0]), "+f"(c[1]), "+f"(c[2]), "+f"(c[3])
        : "r"(a[0]), "r"(a[1]), "r"(a[2]), "r"(a[3]), "r"(b[0]), "r"(b[1]));
}

__device__ __forceinline__ void cp_async16(uint32_t dst, const void* src) {
    asm volatile("cp.async.cg.shared.global [%0], [%1], 16;\n"
                 :: "r"(dst), "l"(src));
}

__device__ __forceinline__ void ldsm_x4(uint32_t r[4], uint32_t addr) {
    asm volatile("ldmatrix.sync.aligned.m8n8.x4.shared.b16 {%0,%1,%2,%3}, [%4];"
                 : "=r"(r[0]), "=r"(r[1]), "=r"(r[2]), "=r"(r[3]) : "r"(addr));
}

// ---------------------------------------------------------------------------
// Prepass kernels
// ---------------------------------------------------------------------------
__global__ __launch_bounds__(256) void round_tf32_kernel(
    const float* __restrict__ in, float* __restrict__ out, int n4)
{
    int i = blockIdx.x * blockDim.x + threadIdx.x;
    if (i < n4) {
        float4 v = ((const float4*)in)[i];
        v.x = to_tf32(v.x); v.y = to_tf32(v.y);
        v.z = to_tf32(v.z); v.w = to_tf32(v.w);
        ((float4*)out)[i] = v;
    }
}

// out[n][k] = tf32(in[k][n]) ; 1024x1024, one matrix per blockIdx.z
__global__ __launch_bounds__(256) void round_transpose_kernel(
    const float* __restrict__ w0, const float* __restrict__ w1,
    const float* __restrict__ w2, const float* __restrict__ w3,
    float* __restrict__ out4)
{
    __shared__ float tile[32][33];
    const float* in = (blockIdx.z == 0) ? w0 : (blockIdx.z == 1) ? w1 :
                      (blockIdx.z == 2) ? w2 : w3;
    float* out = out4 + (size_t)blockIdx.z * HIDDEN * HIDDEN;
    int k0 = blockIdx.x * 32, n0 = blockIdx.y * 32;
    int tx = threadIdx.x & 31, ty = threadIdx.x >> 5;     // 32 x 8
#pragma unroll
    for (int i = 0; i < 32; i += 8)
        tile[ty + i][tx] = in[(size_t)(k0 + ty + i) * HIDDEN + n0 + tx];
    __syncthreads();
#pragma unroll
    for (int i = 0; i < 32; i += 8)
        out[(size_t)(n0 + ty + i) * HIDDEN + k0 + tx] = to_tf32(tile[tx][ty + i]);
}

// ---------------------------------------------------------------------------
// tf32 GEMM: C[M,N] = A[M,K] @ Bt[N,K]^T + bias[N]
// Block tile 128x128, BK=32, 3-stage cp.async pipeline, 256 threads (8 warps
// 2x4), warp tile 64x32. Both tiles stored [row][k] stride 36 (conflict-free
// for ldmatrix: 8 rows hit starting banks 4r+kb, bijective mod 32).
// Fragments loaded with ldmatrix.x4 (b16 view == tf32 frag layout).
// ---------------------------------------------------------------------------
#define GK 1024
#define GN 1024
#define TS_STRIDE 36
#define T_SIZE (128 * TS_STRIDE)                 // 4608 floats per tile
#define STAGE_SIZE (2 * T_SIZE)                  // A + B
#define GEMM_SMEM_BYTES (3 * STAGE_SIZE * (int)sizeof(float))   // 110592

__device__ __forceinline__ void gemm_body_pipe(
    const float* __restrict__ A, const float* __restrict__ Bt,
    const float* __restrict__ bias, float* __restrict__ C, float* sm)
{
    const int tid  = threadIdx.x;
    const int lane = tid & 31;
    const int wid  = tid >> 5;
    const int wm   = wid >> 2;             // 0..1
    const int wn   = wid & 3;              // 0..3
    const int qq   = lane >> 2;
    const int qk   = lane & 3;
    const int brow = blockIdx.y * 128;
    const int bcol = blockIdx.x * 128;

    const int la_r  = tid >> 3;            // 0..31 (+32*i)
    const int la_c4 = (tid & 7) << 2;      // 0,4,...,28

    // ldmatrix lane-address components
    const int g  = lane >> 3;              // matrix index 0..3
    const int lr = lane & 7;               // row within matrix
    const int a_row = lr + (g & 1) * 8;    // A: matrices 0,1 = rows, 2,3 = +4 cols
    const int a_col = (g >> 1) * 4;
    const int b_row = lr + (g >> 1) * 8;   // B: matrices 0,1 = first n8, 2,3 = second
    const int b_col = (g & 1) * 4;

    const uint32_t sm_u = (uint32_t)__cvta_generic_to_shared(sm);

    float acc[4][4][4];
#pragma unroll
    for (int i = 0; i < 4; i++)
#pragma unroll
        for (int j = 0; j < 4; j++)
#pragma unroll
            for (int t = 0; t < 4; t++) acc[i][j][t] = 0.f;

    auto issue = [&](int slot, int k0) {
        uint32_t as_u = sm_u + (uint32_t)(slot * STAGE_SIZE) * 4u;
        uint32_t bs_u = as_u + (uint32_t)T_SIZE * 4u;
#pragma unroll
        for (int i = 0; i < 4; i++) {
            int r = la_r + i * 32;
            cp_async16(as_u + (uint32_t)(r * TS_STRIDE + la_c4) * 4u,
                       A + (size_t)(brow + r) * GK + k0 + la_c4);
        }
#pragma unroll
        for (int i = 0; i < 4; i++) {
            int r = la_r + i * 32;
            cp_async16(bs_u + (uint32_t)(r * TS_STRIDE + la_c4) * 4u,
                       Bt + (size_t)(bcol + r) * GK + k0 + la_c4);
        }
        asm volatile("cp.async.commit_group;\n" ::: "memory");
    };

    issue(0, 0);
    issue(1, 32);

    for (int t = 0; t < 32; t++) {
        if (t == 31)
            asm volatile("cp.async.wait_group 0;\n" ::: "memory");
        else
            asm volatile("cp.async.wait_group 1;\n" ::: "memory");
        __syncthreads();

        if (t + 2 < 32)
            issue((t + 2) % 3, (t + 2) * 32);

        const int slot = t % 3;
        const uint32_t as_u = sm_u + (uint32_t)(slot * STAGE_SIZE) * 4u;
        const uint32_t bs_u = as_u + (uint32_t)T_SIZE * 4u;
        // per-warp lane base addresses (bytes)
        const uint32_t a_base = as_u + (uint32_t)(((wm * 64 + a_row) * TS_STRIDE + a_col)) * 4u;
        const uint32_t b_base = bs_u + (uint32_t)(((wn * 32 + b_row) * TS_STRIDE + b_col)) * 4u;

#pragma unroll
        for (int ks = 0; ks < 4; ks++) {
            const uint32_t kboff = (uint32_t)(ks * 8) * 4u;
            uint32_t af[4][4];
#pragma unroll
            for (int mt = 0; mt < 4; mt++)
                ldsm_x4(af[mt], a_base + (uint32_t)(mt * 16 * TS_STRIDE) * 4u + kboff);
            uint32_t bf[2][4];
#pragma unroll
            for (int ntp = 0; ntp < 2; ntp++)
                ldsm_x4(bf[ntp], b_base + (uint32_t)(ntp * 16 * TS_STRIDE) * 4u + kboff);
#pragma unroll
            for (int mt = 0; mt < 4; mt++)
#pragma unroll
                for (int nt = 0; nt < 4; nt++)
                    mma_tf32(acc[mt][nt], af[mt], &bf[nt >> 1][(nt & 1) * 2]);
        }
        __syncthreads();
    }

    // epilogue
#pragma unroll
    for (int nt = 0; nt < 4; nt++) {
        int cc = bcol + wn * 32 + nt * 8 + 2 * qk;
        float2 bv = *(const float2*)(bias + cc);
#pragma unroll
        for (int mt = 0; mt < 4; mt++) {
            int r = brow + wm * 64 + mt * 16 + qq;
            float2 o0 = make_float2(acc[mt][nt][0] + bv.x, acc[mt][nt][1] + bv.y);
            float2 o1 = make_float2(acc[mt][nt][2] + bv.x, acc[mt][nt][3] + bv.y);
            *(float2*)(C + (size_t)r * GN + cc) = o0;
            *(float2*)(C + (size_t)(r + 8) * GN + cc) = o1;
        }
    }
}

__global__ __launch_bounds__(256, 2) void gemm_qkv_kernel(
    const float* __restrict__ X, const float* __restrict__ Wt4,
    const float* __restrict__ bq, const float* __restrict__ bk,
    const float* __restrict__ bv,
    float* __restrict__ Q, float* __restrict__ K, float* __restrict__ V)
{
    extern __shared__ float smg[];
    const float* W = Wt4 + (size_t)blockIdx.z * HIDDEN * HIDDEN;
    const float* b = (blockIdx.z == 0) ? bq : (blockIdx.z == 1) ? bk : bv;
    float*       C = (blockIdx.z == 0) ? Q  : (blockIdx.z == 1) ? K  : V;
    gemm_body_pipe(X, W, b, C, smg);
}

__global__ __launch_bounds__(256, 2) void gemm_o_kernel(
    const float* __restrict__ A, const float* __restrict__ W,
    const float* __restrict__ b, float* __restrict__ C)
{
    extern __shared__ float smg[];
    gemm_body_pipe(A, W, b, C, smg);
}

// ---------------------------------------------------------------------------
// Banded attention (unchanged — mma.sync tf32, hi/lo-compensated P)
// ---------------------------------------------------------------------------
#define PW  68
#define PPW 196
#define ATTN_SMEM_FLOATS (64*PW + 192*PW + 2*64*PPW + 192 + 256 + 256)

__global__ __launch_bounds__(256) void attn_kernel(const float* __restrict__ maskp)
{
    extern __shared__ float sm[];
    float* Qs   = sm;
    float* Ks   = Qs + 64 * PW;
    float* Ph   = Ks + 192 * PW;
    float* Pl   = Ph + 64 * PPW;
    float* vld  = Pl + 64 * PPW;
    float* redM = vld + 192;
    float* redS = redM + 256;

    const int c = blockIdx.x;
    const int h = blockIdx.y;
    const int b = blockIdx.z;
    const int tid  = threadIdx.x;
    const int lane = tid & 31;
    const int wid  = tid >> 5;
    const int wm   = wid >> 2;
    const int wn   = wid & 3;
    const int qq   = lane >> 2;
    const int qk   = lane & 3;

    const size_t headoff = (size_t)h * HDIM;
    const size_t bbase   = (size_t)b * S_LEN;
    const int base = c * 64 - 64;

#pragma unroll
    for (int it = 0; it < 4; it++) {
        int idx = tid + it * 256;
        int r  = idx >> 4;
        int c4 = (idx & 15) << 2;
        float4 v = *(const float4*)(g_Q + (bbase + c * 64 + r) * HIDDEN + headoff + c4);
        float* p = &Qs[r * PW + c4];
        p[0] = to_tf32(v.x); p[1] = to_tf32(v.y);
        p[2] = to_tf32(v.z); p[3] = to_tf32(v.w);
    }
#pragma unroll
    for (int it = 0; it < 12; it++) {
        int idx = tid + it * 256;
        int r  = idx >> 4;
        int c4 = (idx & 15) << 2;
        int jg = base + r;
        float4 kv = make_float4(0.f, 0.f, 0.f, 0.f);
        if (jg >= 0 && jg < S_LEN)
            kv = *(const float4*)(g_K + (bbase + jg) * HIDDEN + headoff + c4);
        float* p = &Ks[r * PW + c4];
        p[0] = to_tf32(kv.x); p[1] = to_tf32(kv.y);
        p[2] = to_tf32(kv.z); p[3] = to_tf32(kv.w);
    }
    if (tid < 192) {
        int jg = base + tid;
        vld[tid] = (jg >= 0 && jg < S_LEN && maskp[b * S_LEN + jg] > 0.f) ? 1.f : 0.f;
    }
    __syncthreads();

    float acc[2][6][4];
#pragma unroll
    for (int mt = 0; mt < 2; mt++)
#pragma unroll
        for (int nt = 0; nt < 6; nt++)
#pragma unroll
            for (int t = 0; t < 4; t++) acc[mt][nt][t] = 0.f;

#pragma unroll
    for (int ks = 0; ks < 8; ks++) {
        const int kb = ks * 8;
        uint32_t af[2][4];
#pragma unroll
        for (int mt = 0; mt < 2; mt++) {
            int r0 = wm * 32 + mt * 16 + qq;
            af[mt][0] = __float_as_uint(Qs[r0 * PW + kb + qk]);
            af[mt][1] = __float_as_uint(Qs[(r0 + 8) * PW + kb + qk]);
            af[mt][2] = __float_as_uint(Qs[r0 * PW + kb + qk + 4]);
            af[mt][3] = __float_as_uint(Qs[(r0 + 8) * PW + kb + qk + 4]);
        }
        uint32_t bf[6][2];
#pragma unroll
        for (int nt = 0; nt < 6; nt++) {
            int n = wn * 48 + nt * 8 + qq;
            bf[nt][0] = __float_as_uint(Ks[n * PW + kb + qk]);
            bf[nt][1] = __float_as_uint(Ks[n * PW + kb + qk + 4]);
        }
#pragma unroll
        for (int mt = 0; mt < 2; mt++)
#pragma unroll
            for (int nt = 0; nt < 6; nt++)
                mma_tf32(acc[mt][nt], af[mt], bf[nt]);
    }

    float mrow[2][2];
#pragma unroll
    for (int mt = 0; mt < 2; mt++)
#pragma unroll
        for (int hf = 0; hf < 2; hf++) mrow[mt][hf] = -1e30f;

#pragma unroll
    for (int mt = 0; mt < 2; mt++)
#pragma unroll
        for (int nt = 0; nt < 6; nt++) {
            int colb = wn * 48 + nt * 8 + 2 * qk;
#pragma unroll
            for (int hf = 0; hf < 2; hf++) {
                int row = wm * 32 + mt * 16 + qq + 8 * hf;
#pragma unroll
                for (int e = 0; e < 2; e++) {
                    int col = colb + e;
                    float v = acc[mt][nt][hf * 2 + e] * 0.125f;
                    bool ok = (col >= row) && (col <= row + 128) && (vld[col] > 0.f);
                    v = ok ? v : -1e9f;
                    acc[mt][nt][hf * 2 + e] = v;
                    mrow[mt][hf] = fmaxf(mrow[mt][hf], v);
                }
            }
        }
#pragma unroll
    for (int mt = 0; mt < 2; mt++)
#pragma unroll
        for (int hf = 0; hf < 2; hf++) {
            float m = mrow[mt][hf];
            m = fmaxf(m, __shfl_xor_sync(0xffffffffu, m, 1));
            m = fmaxf(m, __shfl_xor_sync(0xffffffffu, m, 2));
            mrow[mt][hf] = m;
        }
    if (qk == 0) {
#pragma unroll
        for (int mt = 0; mt < 2; mt++)
#pragma unroll
            for (int hf = 0; hf < 2; hf++)
                redM[wn * 64 + wm * 32 + mt * 16 + qq + 8 * hf] = mrow[mt][hf];
    }
    __syncthreads();

    float gmv[2][2], srow[2][2];
#pragma unroll
    for (int mt = 0; mt < 2; mt++)
#pragma unroll
        for (int hf = 0; hf < 2; hf++) {
            int row = wm * 32 + mt * 16 + qq + 8 * hf;
            float m = fmaxf(fmaxf(redM[row], redM[64 + row]),
                            fmaxf(redM[128 + row], redM[192 + row]));
            gmv[mt][hf] = m;
            srow[mt][hf] = 0.f;
        }

#pragma unroll
    for (int mt = 0; mt < 2; mt++)
#pragma unroll
        for (int nt = 0; nt < 6; nt++) {
            int colb = wn * 48 + nt * 8 + 2 * qk;
#pragma unroll
            for (int hf = 0; hf < 2; hf++) {
                int row = wm * 32 + mt * 16 + qq + 8 * hf;
                float p0 = __expf(acc[mt][nt][hf * 2 + 0] - gmv[mt][hf]);
                float p1 = __expf(acc[mt][nt][hf * 2 + 1] - gmv[mt][hf]);
                srow[mt][hf] += p0 + p1;
                float h0 = to_tf32(p0), h1 = to_tf32(p1);
                *(float2*)&Ph[row * PPW + colb] = make_float2(h0, h1);
                *(float2*)&Pl[row * PPW + colb] = make_float2(to_tf32(p0 - h0),
                                                             to_tf32(p1 - h1));
            }
        }

#pragma unroll
    for (int mt = 0; mt < 2; mt++)
#pragma unroll
        for (int hf = 0; hf < 2; hf++) {
            float s = srow[mt][hf];
            s += __shfl_xor_sync(0xffffffffu, s, 1);
            s += __shfl_xor_sync(0xffffffffu, s, 2);
            srow[mt][hf] = s;
        }
    if (qk == 0) {
#pragma unroll
        for (int mt = 0; mt < 2; mt++)
#pragma unroll
            for (int hf = 0; hf < 2; hf++)
                redS[wn * 64 + wm * 32 + mt * 16 + qq + 8 * hf] = srow[mt][hf];
    }

#pragma unroll
    for (int it = 0; it < 12; it++) {
        int idx = tid + it * 256;
        int r  = idx >> 4;
        int c4 = (idx & 15) << 2;
        int jg = base + r;
        float4 vv = make_float4(0.f, 0.f, 0.f, 0.f);
        if (jg >= 0 && jg < S_LEN)
            vv = *(const float4*)(g_V + (bbase + jg) * HIDDEN + headoff + c4);
        float* p = &Ks[r * PW + c4];
        p[0] = to_tf32(vv.x); p[1] = to_tf32(vv.y);
        p[2] = to_tf32(vv.z); p[3] = to_tf32(vv.w);
    }
    __syncthreads();

    float c2[2][2][4];
#pragma unroll
    for (int mt = 0; mt < 2; mt++)
#pragma unroll
        for (int nt = 0; nt < 2; nt++)
#pragma unroll
            for (int t = 0; t < 4; t++) c2[mt][nt][t] = 0.f;

#pragma unroll
    for (int ks = 0; ks < 24; ks++) {
        const int kb = ks * 8;
        uint32_t ah[2][4], al[2][4];
#pragma unroll
        for (int mt = 0; mt < 2; mt++) {
            int r0 = wm * 32 + mt * 16 + qq;
            ah[mt][0] = __float_as_uint(Ph[r0 * PPW + kb + qk]);
            ah[mt][1] = __float_as_uint(Ph[(r0 + 8) * PPW + kb + qk]);
            ah[mt][2] = __float_as_uint(Ph[r0 * PPW + kb + qk + 4]);
            ah[mt][3] = __float_as_uint(Ph[(r0 + 8) * PPW + kb + qk + 4]);
            al[mt][0] = __float_as_uint(Pl[r0 * PPW + kb + qk]);
            al[mt][1] = __float_as_uint(Pl[(r0 + 8) * PPW + kb + qk]);
            al[mt][2] = __float_as_uint(Pl[r0 * PPW + kb + qk + 4]);
            al[mt][3] = __float_as_uint(Pl[(r0 + 8) * PPW + kb + qk + 4]);
        }
        uint32_t bf[2][2];
#pragma unroll
        for (int nt = 0; nt < 2; nt++) {
            int n = wn * 16 + nt * 8 + qq;
            bf[nt][0] = __float_as_uint(Ks[(kb + qk) * PW + n]);
            bf[nt][1] = __float_as_uint(Ks[(kb + qk + 4) * PW + n]);
        }
#pragma unroll
        for (int mt = 0; mt < 2; mt++)
#pragma unroll
            for (int nt = 0; nt < 2; nt++) {
                mma_tf32(c2[mt][nt], ah[mt], bf[nt]);
                mma_tf32(c2[mt][nt], al[mt], bf[nt]);
            }
    }

#pragma unroll
    for (int mt = 0; mt < 2; mt++)
#pragma unroll
        for (int hf = 0; hf < 2; hf++) {
            int row = wm * 32 + mt * 16 + qq + 8 * hf;
            float s = redS[row] + redS[64 + row] + redS[128 + row] + redS[192 + row];
            float rinv = 1.f / s;
            float* Og = g_ctx + (bbase + c * 64 + row) * HIDDEN + headoff;
#pragma unroll
            for (int nt = 0; nt < 2; nt++) {
                int col = wn * 16 + nt * 8 + 2 * qk;
                *(float2*)(Og + col) = make_float2(
                    to_tf32(c2[mt][nt][hf * 2 + 0] * rinv),
                    to_tf32(c2[mt][nt][hf * 2 + 1] * rinv));
            }
        }
}

// ---------------------------------------------------------------------------
extern "C" void kernel_launch(void* const* d_in, const int* in_sizes, int n_in,
                              void* d_out, int out_size)
{
    const float* X    = (const float*)d_in[0];
    const float* mask = (const float*)d_in[1];
    const float* Wq   = (const float*)d_in[2];
    const float* bq   = (const float*)d_in[3];
    const float* Wk   = (const float*)d_in[4];
    const float* bk   = (const float*)d_in[5];
    const float* Wv   = (const float*)d_in[6];
    const float* bv   = (const float*)d_in[7];
    const float* Wo   = (const float*)d_in[8];
    const float* bo   = (const float*)d_in[9];
    float* out = (float*)d_out;

    float *qp, *kp, *vp, *cp, *xrp, *wtp;
    cudaGetSymbolAddress((void**)&qp, g_Q);
    cudaGetSymbolAddress((void**)&kp, g_K);
    cudaGetSymbolAddress((void**)&vp, g_V);
    cudaGetSymbolAddress((void**)&cp, g_ctx);
    cudaGetSymbolAddress((void**)&xrp, g_Xr);
    cudaGetSymbolAddress((void**)&wtp, g_Wt);
    float* wt_o = wtp + 3 * (size_t)HIDDEN * HIDDEN;

    const int attn_smem = ATTN_SMEM_FLOATS * (int)sizeof(float);
    cudaFuncSetAttribute(attn_kernel, cudaFuncAttributeMaxDynamicSharedMemorySize,
                         attn_smem);
    cudaFuncSetAttribute(gemm_qkv_kernel, cudaFuncAttributeMaxDynamicSharedMemorySize,
                         GEMM_SMEM_BYTES);
    cudaFuncSetAttribute(gemm_o_kernel, cudaFuncAttributeMaxDynamicSharedMemorySize,
                         GEMM_SMEM_BYTES);

    // ---- prepass: round X; round+transpose weights
    const int xN4 = MROWS * HIDDEN / 4;
    round_tf32_kernel<<<(xN4 + 255) / 256, 256>>>(X, xrp, xN4);
    dim3 tgrid(HIDDEN / 32, HIDDEN / 32, 4);
    round_transpose_kernel<<<tgrid, 256>>>(Wq, Wk, Wv, Wo, wtp);

    dim3 gblk(256);
    dim3 gqkv(HIDDEN / 128, MROWS / 128, 3);       // 8 x 64 x 3
    gemm_qkv_kernel<<<gqkv, gblk, GEMM_SMEM_BYTES>>>(xrp, wtp, bq, bk, bv, qp, kp, vp);

    dim3 agrid(NCHUNK, NHEAD, BATCH);
    attn_kernel<<<agrid, gblk, attn_smem>>>(mask);

    dim3 go(HIDDEN / 128, MROWS / 128);            // 8 x 64
    gemm_o_kernel<<<go, gblk, GEMM_SMEM_BYTES>>>(cp, wt_o, bo, out);
}

// round 8
// speedup vs baseline: 1.1326x; 1.0643x over previous
#include <cuda_runtime.h>
#include <cstdint>

// ---------------------------------------------------------------------------
// LongformerAttention  B=2, S=4096, HID=1024, H=16, D=64, W=64
// Round 8: attention smem overlay (105KB -> 2 blocks/SM) + single-tf32 P
// (Phase-B MMA count halved). GEMMs unchanged from R7 (ldmatrix + 3-stage).
// ---------------------------------------------------------------------------

#define S_LEN   4096
#define HIDDEN  1024
#define NHEAD   16
#define HDIM    64
#define NCHUNK  64
#define BATCH   2
#define MROWS   (BATCH * S_LEN)   // 8192

__device__ float g_Q[(size_t)MROWS * HIDDEN];
__device__ float g_K[(size_t)MROWS * HIDDEN];
__device__ float g_V[(size_t)MROWS * HIDDEN];
__device__ float g_ctx[(size_t)MROWS * HIDDEN];
__device__ float g_Xr[(size_t)MROWS * HIDDEN];          // tf32-rounded X
__device__ float g_Wt[4][(size_t)HIDDEN * HIDDEN];      // tf32-rounded, TRANSPOSED W [n][k]

__device__ __forceinline__ float to_tf32(float x) {
    float y;
    asm("cvt.rna.tf32.f32 %0, %1;" : "=f"(y) : "f"(x));
    return y;
}

__device__ __forceinline__ void mma_tf32(float c[4], const uint32_t a[4], const uint32_t b[2]) {
    asm volatile(
        "mma.sync.aligned.m16n8k8.row.col.f32.tf32.tf32.f32 "
        "{%0,%1,%2,%3}, {%4,%5,%6,%7}, {%8,%9}, {%0,%1,%2,%3};"
        : "+f"(c[0]), "+f"(c[1]), "+f"(c[2]), "+f"(c[3])
        : "r"(a[0]), "r"(a[1]), "r"(a[2]), "r"(a[3]), "r"(b[0]), "r"(b[1]));
}

__device__ __forceinline__ void cp_async16(uint32_t dst, const void* src) {
    asm volatile("cp.async.cg.shared.global [%0], [%1], 16;\n"
                 :: "r"(dst), "l"(src));
}

__device__ __forceinline__ void ldsm_x4(uint32_t r[4], uint32_t addr) {
    asm volatile("ldmatrix.sync.aligned.m8n8.x4.shared.b16 {%0,%1,%2,%3}, [%4];"
                 : "=r"(r[0]), "=r"(r[1]), "=r"(r[2]), "=r"(r[3]) : "r"(addr));
}

// ---------------------------------------------------------------------------
// Prepass kernels
// ---------------------------------------------------------------------------
__global__ __launch_bounds__(256) void round_tf32_kernel(
    const float* __restrict__ in, float* __restrict__ out, int n4)
{
    int i = blockIdx.x * blockDim.x + threadIdx.x;
    if (i < n4) {
        float4 v = ((const float4*)in)[i];
        v.x = to_tf32(v.x); v.y = to_tf32(v.y);
        v.z = to_tf32(v.z); v.w = to_tf32(v.w);
        ((float4*)out)[i] = v;
    }
}

// out[n][k] = tf32(in[k][n]) ; 1024x1024, one matrix per blockIdx.z
__global__ __launch_bounds__(256) void round_transpose_kernel(
    const float* __restrict__ w0, const float* __restrict__ w1,
    const float* __restrict__ w2, const float* __restrict__ w3,
    float* __restrict__ out4)
{
    __shared__ float tile[32][33];
    const float* in = (blockIdx.z == 0) ? w0 : (blockIdx.z == 1) ? w1 :
                      (blockIdx.z == 2) ? w2 : w3;
    float* out = out4 + (size_t)blockIdx.z * HIDDEN * HIDDEN;
    int k0 = blockIdx.x * 32, n0 = blockIdx.y * 32;
    int tx = threadIdx.x & 31, ty = threadIdx.x >> 5;     // 32 x 8
#pragma unroll
    for (int i = 0; i < 32; i += 8)
        tile[ty + i][tx] = in[(size_t)(k0 + ty + i) * HIDDEN + n0 + tx];
    __syncthreads();
#pragma unroll
    for (int i = 0; i < 32; i += 8)
        out[(size_t)(n0 + ty + i) * HIDDEN + k0 + tx] = to_tf32(tile[tx][ty + i]);
}

// ---------------------------------------------------------------------------
// tf32 GEMM (unchanged from R7): C[M,N] = A[M,K] @ Bt[N,K]^T + bias[N]
// ---------------------------------------------------------------------------
#define GK 1024
#define GN 1024
#define TS_STRIDE 36
#define T_SIZE (128 * TS_STRIDE)
#define STAGE_SIZE (2 * T_SIZE)
#define GEMM_SMEM_BYTES (3 * STAGE_SIZE * (int)sizeof(float))   // 110592

__device__ __forceinline__ void gemm_body_pipe(
    const float* __restrict__ A, const float* __restrict__ Bt,
    const float* __restrict__ bias, float* __restrict__ C, float* sm)
{
    const int tid  = threadIdx.x;
    const int lane = tid & 31;
    const int wid  = tid >> 5;
    const int wm   = wid >> 2;
    const int wn   = wid & 3;
    const int qq   = lane >> 2;
    const int qk   = lane & 3;
    const int brow = blockIdx.y * 128;
    const int bcol = blockIdx.x * 128;

    const int la_r  = tid >> 3;
    const int la_c4 = (tid & 7) << 2;

    const int g  = lane >> 3;
    const int lr = lane & 7;
    const int a_row = lr + (g & 1) * 8;
    const int a_col = (g >> 1) * 4;
    const int b_row = lr + (g >> 1) * 8;
    const int b_col = (g & 1) * 4;

    const uint32_t sm_u = (uint32_t)__cvta_generic_to_shared(sm);

    float acc[4][4][4];
#pragma unroll
    for (int i = 0; i < 4; i++)
#pragma unroll
        for (int j = 0; j < 4; j++)
#pragma unroll
            for (int t = 0; t < 4; t++) acc[i][j][t] = 0.f;

    auto issue = [&](int slot, int k0) {
        uint32_t as_u = sm_u + (uint32_t)(slot * STAGE_SIZE) * 4u;
        uint32_t bs_u = as_u + (uint32_t)T_SIZE * 4u;
#pragma unroll
        for (int i = 0; i < 4; i++) {
            int r = la_r + i * 32;
            cp_async16(as_u + (uint32_t)(r * TS_STRIDE + la_c4) * 4u,
                       A + (size_t)(brow + r) * GK + k0 + la_c4);
        }
#pragma unroll
        for (int i = 0; i < 4; i++) {
            int r = la_r + i * 32;
            cp_async16(bs_u + (uint32_t)(r * TS_STRIDE + la_c4) * 4u,
                       Bt + (size_t)(bcol + r) * GK + k0 + la_c4);
        }
        asm volatile("cp.async.commit_group;\n" ::: "memory");
    };

    issue(0, 0);
    issue(1, 32);

    for (int t = 0; t < 32; t++) {
        if (t == 31)
            asm volatile("cp.async.wait_group 0;\n" ::: "memory");
        else
            asm volatile("cp.async.wait_group 1;\n" ::: "memory");
        __syncthreads();

        if (t + 2 < 32)
            issue((t + 2) % 3, (t + 2) * 32);

        const int slot = t % 3;
        const uint32_t as_u = sm_u + (uint32_t)(slot * STAGE_SIZE) * 4u;
        const uint32_t bs_u = as_u + (uint32_t)T_SIZE * 4u;
        const uint32_t a_base = as_u + (uint32_t)(((wm * 64 + a_row) * TS_STRIDE + a_col)) * 4u;
        const uint32_t b_base = bs_u + (uint32_t)(((wn * 32 + b_row) * TS_STRIDE + b_col)) * 4u;

#pragma unroll
        for (int ks = 0; ks < 4; ks++) {
            const uint32_t kboff = (uint32_t)(ks * 8) * 4u;
            uint32_t af[4][4];
#pragma unroll
            for (int mt = 0; mt < 4; mt++)
                ldsm_x4(af[mt], a_base + (uint32_t)(mt * 16 * TS_STRIDE) * 4u + kboff);
            uint32_t bf[2][4];
#pragma unroll
            for (int ntp = 0; ntp < 2; ntp++)
                ldsm_x4(bf[ntp], b_base + (uint32_t)(ntp * 16 * TS_STRIDE) * 4u + kboff);
#pragma unroll
            for (int mt = 0; mt < 4; mt++)
#pragma unroll
                for (int nt = 0; nt < 4; nt++)
                    mma_tf32(acc[mt][nt], af[mt], &bf[nt >> 1][(nt & 1) * 2]);
        }
        __syncthreads();
    }

#pragma unroll
    for (int nt = 0; nt < 4; nt++) {
        int cc = bcol + wn * 32 + nt * 8 + 2 * qk;
        float2 bv = *(const float2*)(bias + cc);
#pragma unroll
        for (int mt = 0; mt < 4; mt++) {
            int r = brow + wm * 64 + mt * 16 + qq;
            float2 o0 = make_float2(acc[mt][nt][0] + bv.x, acc[mt][nt][1] + bv.y);
            float2 o1 = make_float2(acc[mt][nt][2] + bv.x, acc[mt][nt][3] + bv.y);
            *(float2*)(C + (size_t)r * GN + cc) = o0;
            *(float2*)(C + (size_t)(r + 8) * GN + cc) = o1;
        }
    }
}

__global__ __launch_bounds__(256, 2) void gemm_qkv_kernel(
    const float* __restrict__ X, const float* __restrict__ Wt4,
    const float* __restrict__ bq, const float* __restrict__ bk,
    const float* __restrict__ bv,
    float* __restrict__ Q, float* __restrict__ K, float* __restrict__ V)
{
    extern __shared__ float smg[];
    const float* W = Wt4 + (size_t)blockIdx.z * HIDDEN * HIDDEN;
    const float* b = (blockIdx.z == 0) ? bq : (blockIdx.z == 1) ? bk : bv;
    float*       C = (blockIdx.z == 0) ? Q  : (blockIdx.z == 1) ? K  : V;
    gemm_body_pipe(X, W, b, C, smg);
}

__global__ __launch_bounds__(256, 2) void gemm_o_kernel(
    const float* __restrict__ A, const float* __restrict__ W,
    const float* __restrict__ b, float* __restrict__ C)
{
    extern __shared__ float smg[];
    gemm_body_pipe(A, W, b, C, smg);
}

// ---------------------------------------------------------------------------
// Banded attention, overlay layout (105.2KB -> 2 blocks/SM), single-tf32 P.
// Phase A: Qs [0,4352), Ks [4352,17408).  (both dead after the redM sync)
// Phase B: Ph [0,12544) stride 196, Vs [12544,25600) stride 68.
// misc at 25600: vld 192 | redM 256 | redS 256.  Total 26304 floats.
// ---------------------------------------------------------------------------
#define PW  68
#define PPW 196
#define QS_OFF   0
#define KS_OFF   4352
#define PH_OFF   0
#define VS_OFF   12544
#define MISC_OFF 25600
#define ATTN_SMEM_FLOATS (MISC_OFF + 704)

__global__ __launch_bounds__(256) void attn_kernel(const float* __restrict__ maskp)
{
    extern __shared__ float sm[];
    float* Qs   = sm + QS_OFF;           // 64 x 68
    float* Ks   = sm + KS_OFF;           // 192 x 68
    float* Ph   = sm + PH_OFF;           // 64 x 196  (overlays Qs+Ks head)
    float* Vs   = sm + VS_OFF;           // 192 x 68  (overlays Ks tail)
    float* vld  = sm + MISC_OFF;         // 192
    float* redM = vld + 192;             // 256
    float* redS = redM + 256;            // 256

    const int c = blockIdx.x;
    const int h = blockIdx.y;
    const int b = blockIdx.z;
    const int tid  = threadIdx.x;
    const int lane = tid & 31;
    const int wid  = tid >> 5;
    const int wm   = wid >> 2;
    const int wn   = wid & 3;
    const int qq   = lane >> 2;
    const int qk   = lane & 3;

    const size_t headoff = (size_t)h * HDIM;
    const size_t bbase   = (size_t)b * S_LEN;
    const int base = c * 64 - 64;

    // ---- load Q (64x64) and K (192x64) as tf32
#pragma unroll
    for (int it = 0; it < 4; it++) {
        int idx = tid + it * 256;
        int r  = idx >> 4;
        int c4 = (idx & 15) << 2;
        float4 v = *(const float4*)(g_Q + (bbase + c * 64 + r) * HIDDEN + headoff + c4);
        float* p = &Qs[r * PW + c4];
        p[0] = to_tf32(v.x); p[1] = to_tf32(v.y);
        p[2] = to_tf32(v.z); p[3] = to_tf32(v.w);
    }
#pragma unroll
    for (int it = 0; it < 12; it++) {
        int idx = tid + it * 256;
        int r  = idx >> 4;
        int c4 = (idx & 15) << 2;
        int jg = base + r;
        float4 kv = make_float4(0.f, 0.f, 0.f, 0.f);
        if (jg >= 0 && jg < S_LEN)
            kv = *(const float4*)(g_K + (bbase + jg) * HIDDEN + headoff + c4);
        float* p = &Ks[r * PW + c4];
        p[0] = to_tf32(kv.x); p[1] = to_tf32(kv.y);
        p[2] = to_tf32(kv.z); p[3] = to_tf32(kv.w);
    }
    if (tid < 192) {
        int jg = base + tid;
        vld[tid] = (jg >= 0 && jg < S_LEN && maskp[b * S_LEN + jg] > 0.f) ? 1.f : 0.f;
    }
    __syncthreads();

    // ---- Phase A: S = Q K^T  (warp rows wm*32..+32, cols wn*48..+48)
    float acc[2][6][4];
#pragma unroll
    for (int mt = 0; mt < 2; mt++)
#pragma unroll
        for (int nt = 0; nt < 6; nt++)
#pragma unroll
            for (int t = 0; t < 4; t++) acc[mt][nt][t] = 0.f;

#pragma unroll
    for (int ks = 0; ks < 8; ks++) {
        const int kb = ks * 8;
        uint32_t af[2][4];
#pragma unroll
        for (int mt = 0; mt < 2; mt++) {
            int r0 = wm * 32 + mt * 16 + qq;
            af[mt][0] = __float_as_uint(Qs[r0 * PW + kb + qk]);
            af[mt][1] = __float_as_uint(Qs[(r0 + 8) * PW + kb + qk]);
            af[mt][2] = __float_as_uint(Qs[r0 * PW + kb + qk + 4]);
            af[mt][3] = __float_as_uint(Qs[(r0 + 8) * PW + kb + qk + 4]);
        }
        uint32_t bf[6][2];
#pragma unroll
        for (int nt = 0; nt < 6; nt++) {
            int n = wn * 48 + nt * 8 + qq;
            bf[nt][0] = __float_as_uint(Ks[n * PW + kb + qk]);
            bf[nt][1] = __float_as_uint(Ks[n * PW + kb + qk + 4]);
        }
#pragma unroll
        for (int mt = 0; mt < 2; mt++)
#pragma unroll
            for (int nt = 0; nt < 6; nt++)
                mma_tf32(acc[mt][nt], af[mt], bf[nt]);
    }

    // ---- scale + band/valid mask + row-max partials
    float mrow[2][2];
#pragma unroll
    for (int mt = 0; mt < 2; mt++)
#pragma unroll
        for (int hf = 0; hf < 2; hf++) mrow[mt][hf] = -1e30f;

#pragma unroll
    for (int mt = 0; mt < 2; mt++)
#pragma unroll
        for (int nt = 0; nt < 6; nt++) {
            int colb = wn * 48 + nt * 8 + 2 * qk;
#pragma unroll
            for (int hf = 0; hf < 2; hf++) {
                int row = wm * 32 + mt * 16 + qq + 8 * hf;
#pragma unroll
                for (int e = 0; e < 2; e++) {
                    int col = colb + e;
                    float v = acc[mt][nt][hf * 2 + e] * 0.125f;
                    bool ok = (col >= row) && (col <= row + 128) && (vld[col] > 0.f);
                    v = ok ? v : -1e9f;
                    acc[mt][nt][hf * 2 + e] = v;
                    mrow[mt][hf] = fmaxf(mrow[mt][hf], v);
                }
            }
        }
#pragma unroll
    for (int mt = 0; mt < 2; mt++)
#pragma unroll
        for (int hf = 0; hf < 2; hf++) {
            float m = mrow[mt][hf];
            m = fmaxf(m, __shfl_xor_sync(0xffffffffu, m, 1));
            m = fmaxf(m, __shfl_xor_sync(0xffffffffu, m, 2));
            mrow[mt][hf] = m;
        }
    if (qk == 0) {
#pragma unroll
        for (int mt = 0; mt < 2; mt++)
#pragma unroll
            for (int hf = 0; hf < 2; hf++)
                redM[wn * 64 + wm * 32 + mt * 16 + qq + 8 * hf] = mrow[mt][hf];
    }
    __syncthreads();   // redM ready; ALL Qs/Ks fragment reads complete -> overlay safe

    // ---- global row max, exp, single-tf32 P store (over Qs/Ks), row sums; V load
    float gmv[2][2], srow[2][2];
#pragma unroll
    for (int mt = 0; mt < 2; mt++)
#pragma unroll
        for (int hf = 0; hf < 2; hf++) {
            int row = wm * 32 + mt * 16 + qq + 8 * hf;
            float m = fmaxf(fmaxf(redM[row], redM[64 + row]),
                            fmaxf(redM[128 + row], redM[192 + row]));
            gmv[mt][hf] = m;
            srow[mt][hf] = 0.f;
        }

#pragma unroll
    for (int mt = 0; mt < 2; mt++)
#pragma unroll
        for (int nt = 0; nt < 6; nt++) {
            int colb = wn * 48 + nt * 8 + 2 * qk;
#pragma unroll
            for (int hf = 0; hf < 2; hf++) {
                int row = wm * 32 + mt * 16 + qq + 8 * hf;
                float h0 = to_tf32(__expf(acc[mt][nt][hf * 2 + 0] - gmv[mt][hf]));
                float h1 = to_tf32(__expf(acc[mt][nt][hf * 2 + 1] - gmv[mt][hf]));
                srow[mt][hf] += h0 + h1;
                *(float2*)&Ph[row * PPW + colb] = make_float2(h0, h1);
            }
        }

#pragma unroll
    for (int mt = 0; mt < 2; mt++)
#pragma unroll
        for (int hf = 0; hf < 2; hf++) {
            float s = srow[mt][hf];
            s += __shfl_xor_sync(0xffffffffu, s, 1);
            s += __shfl_xor_sync(0xffffffffu, s, 2);
            srow[mt][hf] = s;
        }
    if (qk == 0) {
#pragma unroll
        for (int mt = 0; mt < 2; mt++)
#pragma unroll
            for (int hf = 0; hf < 2; hf++)
                redS[wn * 64 + wm * 32 + mt * 16 + qq + 8 * hf] = srow[mt][hf];
    }

    // V tile into fresh region (disjoint from Ph)
#pragma unroll
    for (int it = 0; it < 12; it++) {
        int idx = tid + it * 256;
        int r  = idx >> 4;
        int c4 = (idx & 15) << 2;
        int jg = base + r;
        float4 vv = make_float4(0.f, 0.f, 0.f, 0.f);
        if (jg >= 0 && jg < S_LEN)
            vv = *(const float4*)(g_V + (bbase + jg) * HIDDEN + headoff + c4);
        float* p = &Vs[r * PW + c4];
        p[0] = to_tf32(vv.x); p[1] = to_tf32(vv.y);
        p[2] = to_tf32(vv.z); p[3] = to_tf32(vv.w);
    }
    __syncthreads();   // Ph, redS, Vs all ready

    // ---- Phase B: ctx = P V  (warp rows wm*32..+32, cols wn*16..+16, K=192)
    float c2[2][2][4];
#pragma unroll
    for (int mt = 0; mt < 2; mt++)
#pragma unroll
        for (int nt = 0; nt < 2; nt++)
#pragma unroll
            for (int t = 0; t < 4; t++) c2[mt][nt][t] = 0.f;

#pragma unroll
    for (int ks = 0; ks < 24; ks++) {
        const int kb = ks * 8;
        uint32_t ah[2][4];
#pragma unroll
        for (int mt = 0; mt < 2; mt++) {
            int r0 = wm * 32 + mt * 16 + qq;
            ah[mt][0] = __float_as_uint(Ph[r0 * PPW + kb + qk]);
            ah[mt][1] = __float_as_uint(Ph[(r0 + 8) * PPW + kb + qk]);
            ah[mt][2] = __float_as_uint(Ph[r0 * PPW + kb + qk + 4]);
            ah[mt][3] = __float_as_uint(Ph[(r0 + 8) * PPW + kb + qk + 4]);
        }
        uint32_t bf[2][2];
#pragma unroll
        for (int nt = 0; nt < 2; nt++) {
            int n = wn * 16 + nt * 8 + qq;
            bf[nt][0] = __float_as_uint(Vs[(kb + qk) * PW + n]);
            bf[nt][1] = __float_as_uint(Vs[(kb + qk + 4) * PW + n]);
        }
#pragma unroll
        for (int mt = 0; mt < 2; mt++)
#pragma unroll
            for (int nt = 0; nt < 2; nt++)
                mma_tf32(c2[mt][nt], ah[mt], bf[nt]);
    }

    // ---- epilogue: normalize, tf32-round (feeds cp.async O-proj), store
#pragma unroll
    for (int mt = 0; mt < 2; mt++)
#pragma unroll
        for (int hf = 0; hf < 2; hf++) {
            int row = wm * 32 + mt * 16 + qq + 8 * hf;
            float s = redS[row] + redS[64 + row] + redS[128 + row] + redS[192 + row];
            float rinv = 1.f / s;
            float* Og = g_ctx + (bbase + c * 64 + row) * HIDDEN + headoff;
#pragma unroll
            for (int nt = 0; nt < 2; nt++) {
                int col = wn * 16 + nt * 8 + 2 * qk;
                *(float2*)(Og + col) = make_float2(
                    to_tf32(c2[mt][nt][hf * 2 + 0] * rinv),
                    to_tf32(c2[mt][nt][hf * 2 + 1] * rinv));
            }
        }
}

// ---------------------------------------------------------------------------
extern "C" void kernel_launch(void* const* d_in, const int* in_sizes, int n_in,
                              void* d_out, int out_size)
{
    const float* X    = (const float*)d_in[0];
    const float* mask = (const float*)d_in[1];
    const float* Wq   = (const float*)d_in[2];
    const float* bq   = (const float*)d_in[3];
    const float* Wk   = (const float*)d_in[4];
    const float* bk   = (const float*)d_in[5];
    const float* Wv   = (const float*)d_in[6];
    const float* bv   = (const float*)d_in[7];
    const float* Wo   = (const float*)d_in[8];
    const float* bo   = (const float*)d_in[9];
    float* out = (float*)d_out;

    float *qp, *kp, *vp, *cp, *xrp, *wtp;
    cudaGetSymbolAddress((void**)&qp, g_Q);
    cudaGetSymbolAddress((void**)&kp, g_K);
    cudaGetSymbolAddress((void**)&vp, g_V);
    cudaGetSymbolAddress((void**)&cp, g_ctx);
    cudaGetSymbolAddress((void**)&xrp, g_Xr);
    cudaGetSymbolAddress((void**)&wtp, g_Wt);
    float* wt_o = wtp + 3 * (size_t)HIDDEN * HIDDEN;

    const int attn_smem = ATTN_SMEM_FLOATS * (int)sizeof(float);
    cudaFuncSetAttribute(attn_kernel, cudaFuncAttributeMaxDynamicSharedMemorySize,
                         attn_smem);
    cudaFuncSetAttribute(gemm_qkv_kernel, cudaFuncAttributeMaxDynamicSharedMemorySize,
                         GEMM_SMEM_BYTES);
    cudaFuncSetAttribute(gemm_o_kernel, cudaFuncAttributeMaxDynamicSharedMemorySize,
                         GEMM_SMEM_BYTES);

    // ---- prepass: round X; round+transpose weights
    const int xN4 = MROWS * HIDDEN / 4;
    round_tf32_kernel<<<(xN4 + 255) / 256, 256>>>(X, xrp, xN4);
    dim3 tgrid(HIDDEN / 32, HIDDEN / 32, 4);
    round_transpose_kernel<<<tgrid, 256>>>(Wq, Wk, Wv, Wo, wtp);

    dim3 gblk(256);
    dim3 gqkv(HIDDEN / 128, MROWS / 128, 3);       // 8 x 64 x 3
    gemm_qkv_kernel<<<gqkv, gblk, GEMM_SMEM_BYTES>>>(xrp, wtp, bq, bk, bv, qp, kp, vp);

    dim3 agrid(NCHUNK, NHEAD, BATCH);
    attn_kernel<<<agrid, gblk, attn_smem>>>(mask);

    dim3 go(HIDDEN / 128, MROWS / 128);            // 8 x 64
    gemm_o_kernel<<<go, gblk, GEMM_SMEM_BYTES>>>(cp, wt_o, bo, out);
}

// round 9
// speedup vs baseline: 2.0399x; 1.8012x over previous
#include <cuda_runtime.h>
#include <cuda_fp16.h>
#include <cstdint>

// ---------------------------------------------------------------------------
// LongformerAttention  B=2, S=4096, HID=1024, H=16, D=64, W=64
// Round 9: full fp16 mma.sync pipeline (same 10-bit mantissa as tf32, 2x rate,
// half the smem/gmem traffic). fp32 accumulation everywhere.
// ---------------------------------------------------------------------------

#define S_LEN   4096
#define HIDDEN  1024
#define NHEAD   16
#define HDIM    64
#define NCHUNK  64
#define BATCH   2
#define MROWS   (BATCH * S_LEN)   // 8192

__device__ __half g_Qh[(size_t)MROWS * HIDDEN];
__device__ __half g_Kh[(size_t)MROWS * HIDDEN];
__device__ __half g_Vh[(size_t)MROWS * HIDDEN];
__device__ __half g_ctxh[(size_t)MROWS * HIDDEN];
__device__ __half g_Xh[(size_t)MROWS * HIDDEN];          // fp16 X
__device__ __half g_Wth[4][(size_t)HIDDEN * HIDDEN];     // fp16 TRANSPOSED W [n][k]

__device__ __forceinline__ void mma_f16(float c[4], const uint32_t a[4], const uint32_t b[2]) {
    asm volatile(
        "mma.sync.aligned.m16n8k16.row.col.f32.f16.f16.f32 "
        "{%0,%1,%2,%3}, {%4,%5,%6,%7}, {%8,%9}, {%0,%1,%2,%3};"
        : "+f"(c[0]), "+f"(c[1]), "+f"(c[2]), "+f"(c[3])
        : "r"(a[0]), "r"(a[1]), "r"(a[2]), "r"(a[3]), "r"(b[0]), "r"(b[1]));
}

__device__ __forceinline__ void cp_async16(uint32_t dst, const void* src) {
    asm volatile("cp.async.cg.shared.global [%0], [%1], 16;\n"
                 :: "r"(dst), "l"(src));
}

__device__ __forceinline__ void ldsm_x4(uint32_t r[4], uint32_t addr) {
    asm volatile("ldmatrix.sync.aligned.m8n8.x4.shared.b16 {%0,%1,%2,%3}, [%4];"
                 : "=r"(r[0]), "=r"(r[1]), "=r"(r[2]), "=r"(r[3]) : "r"(addr));
}

__device__ __forceinline__ void ldsm_x4_t(uint32_t r[4], uint32_t addr) {
    asm volatile("ldmatrix.sync.aligned.m8n8.x4.trans.shared.b16 {%0,%1,%2,%3}, [%4];"
                 : "=r"(r[0]), "=r"(r[1]), "=r"(r[2]), "=r"(r[3]) : "r"(addr));
}

// ---------------------------------------------------------------------------
// Prepass: fp32 -> fp16 (X) and fp32 -> fp16 transposed (weights)
// ---------------------------------------------------------------------------
__global__ __launch_bounds__(256) void round_fp16_kernel(
    const float* __restrict__ in, __half* __restrict__ out, int n4)
{
    int i = blockIdx.x * blockDim.x + threadIdx.x;
    if (i < n4) {
        float4 v = ((const float4*)in)[i];
        __half2 h01 = __floats2half2_rn(v.x, v.y);
        __half2 h23 = __floats2half2_rn(v.z, v.w);
        ((__half2*)out)[2 * i]     = h01;
        ((__half2*)out)[2 * i + 1] = h23;
    }
}

// out[n][k] = fp16(in[k][n]) ; 1024x1024, one matrix per blockIdx.z
__global__ __launch_bounds__(256) void round_transpose_kernel(
    const float* __restrict__ w0, const float* __restrict__ w1,
    const float* __restrict__ w2, const float* __restrict__ w3,
    __half* __restrict__ out4)
{
    __shared__ float tile[32][33];
    const float* in = (blockIdx.z == 0) ? w0 : (blockIdx.z == 1) ? w1 :
                      (blockIdx.z == 2) ? w2 : w3;
    __half* out = out4 + (size_t)blockIdx.z * HIDDEN * HIDDEN;
    int k0 = blockIdx.x * 32, n0 = blockIdx.y * 32;
    int tx = threadIdx.x & 31, ty = threadIdx.x >> 5;
#pragma unroll
    for (int i = 0; i < 32; i += 8)
        tile[ty + i][tx] = in[(size_t)(k0 + ty + i) * HIDDEN + n0 + tx];
    __syncthreads();
#pragma unroll
    for (int i = 0; i < 32; i += 8)
        out[(size_t)(n0 + ty + i) * HIDDEN + k0 + tx] = __float2half_rn(tile[tx][ty + i]);
}

// ---------------------------------------------------------------------------
// fp16 GEMM: C[M,N] = A[M,K] @ Bt[N,K]^T + bias[N]
// Block 128x128, BK=64 halves, 3-stage cp.async, 8 warps (2x4), warp 64x32.
// smem rows stride 72 halves (144B: 9r mod 8 bijective -> ldmatrix clean).
// ---------------------------------------------------------------------------
#define GK 1024
#define GN 1024
#define TSH 72
#define T_HALVES (128 * TSH)                    // 9216
#define STAGE_HALVES (2 * T_HALVES)             // 18432
#define GEMM_SMEM_BYTES (3 * STAGE_HALVES * 2)  // 110592

template <bool OUT_HALF>
__device__ __forceinline__ void gemm_body_f16(
    const __half* __restrict__ A, const __half* __restrict__ Bt,
    const float* __restrict__ bias, void* __restrict__ Cv, __half* sm)
{
    const int tid  = threadIdx.x;
    const int lane = tid & 31;
    const int wid  = tid >> 5;
    const int wm   = wid >> 2;
    const int wn   = wid & 3;
    const int qq   = lane >> 2;
    const int qk   = lane & 3;
    const int brow = blockIdx.y * 128;
    const int bcol = blockIdx.x * 128;

    const int g  = lane >> 3;
    const int lr = lane & 7;

    const uint32_t sm_u = (uint32_t)__cvta_generic_to_shared(sm);

    float acc[4][4][4];
#pragma unroll
    for (int i = 0; i < 4; i++)
#pragma unroll
        for (int j = 0; j < 4; j++)
#pragma unroll
            for (int t = 0; t < 4; t++) acc[i][j][t] = 0.f;

    // per-stage load: each tile 128 rows x 64 halves = 1024 x 16B chunks
    auto issue = [&](int slot, int k0) {
        uint32_t as_u = sm_u + (uint32_t)(slot * STAGE_HALVES) * 2u;
        uint32_t bs_u = as_u + (uint32_t)T_HALVES * 2u;
#pragma unroll
        for (int i = 0; i < 4; i++) {
            int idx = tid + i * 256;
            int r = idx >> 3, c = idx & 7;
            cp_async16(as_u + (uint32_t)(r * 144 + c * 16),
                       A + (size_t)(brow + r) * GK + k0 + c * 8);
        }
#pragma unroll
        for (int i = 0; i < 4; i++) {
            int idx = tid + i * 256;
            int r = idx >> 3, c = idx & 7;
            cp_async16(bs_u + (uint32_t)(r * 144 + c * 16),
                       Bt + (size_t)(bcol + r) * GK + k0 + c * 8);
        }
        asm volatile("cp.async.commit_group;\n" ::: "memory");
    };

    issue(0, 0);
    issue(1, 64);

    for (int t = 0; t < 16; t++) {
        if (t == 15)
            asm volatile("cp.async.wait_group 0;\n" ::: "memory");
        else
            asm volatile("cp.async.wait_group 1;\n" ::: "memory");
        __syncthreads();

        if (t + 2 < 16)
            issue((t + 2) % 3, (t + 2) * 64);

        const int slot = t % 3;
        const uint32_t as_u = sm_u + (uint32_t)(slot * STAGE_HALVES) * 2u;
        const uint32_t bs_u = as_u + (uint32_t)T_HALVES * 2u;
        // A frag addr: lanes 0-15 -> rows, k0-7; 16-31 -> rows, k8-15
        const uint32_t a_base = as_u + (uint32_t)((wm * 64 + (lane & 15)) * 144 + (lane >> 4) * 16);
        // B frag addr: matrices [n0-7 k0-7][n0-7 k8-15][n8-15 k0-7][n8-15 k8-15]
        const uint32_t b_base = bs_u + (uint32_t)((wn * 32 + (g >> 1) * 8 + lr) * 144 + (g & 1) * 16);

#pragma unroll
        for (int ks = 0; ks < 4; ks++) {
            const uint32_t kboff = (uint32_t)(ks * 32);   // 16 halves
            uint32_t af[4][4];
#pragma unroll
            for (int mt = 0; mt < 4; mt++)
                ldsm_x4(af[mt], a_base + (uint32_t)(mt * 16 * 144) + kboff);
            uint32_t bf[2][4];
#pragma unroll
            for (int ntp = 0; ntp < 2; ntp++)
                ldsm_x4(bf[ntp], b_base + (uint32_t)(ntp * 16 * 144) + kboff);
#pragma unroll
            for (int mt = 0; mt < 4; mt++)
#pragma unroll
                for (int nt = 0; nt < 4; nt++)
                    mma_f16(acc[mt][nt], af[mt], &bf[nt >> 1][(nt & 1) * 2]);
        }
        __syncthreads();
    }

    // epilogue
#pragma unroll
    for (int nt = 0; nt < 4; nt++) {
        int cc = bcol + wn * 32 + nt * 8 + 2 * qk;
        float2 bv = *(const float2*)(bias + cc);
#pragma unroll
        for (int mt = 0; mt < 4; mt++) {
            int r = brow + wm * 64 + mt * 16 + qq;
            if (OUT_HALF) {
                __half* C = (__half*)Cv;
                *(__half2*)(C + (size_t)r * GN + cc) =
                    __floats2half2_rn(acc[mt][nt][0] + bv.x, acc[mt][nt][1] + bv.y);
                *(__half2*)(C + (size_t)(r + 8) * GN + cc) =
                    __floats2half2_rn(acc[mt][nt][2] + bv.x, acc[mt][nt][3] + bv.y);
            } else {
                float* C = (float*)Cv;
                *(float2*)(C + (size_t)r * GN + cc) =
                    make_float2(acc[mt][nt][0] + bv.x, acc[mt][nt][1] + bv.y);
                *(float2*)(C + (size_t)(r + 8) * GN + cc) =
                    make_float2(acc[mt][nt][2] + bv.x, acc[mt][nt][3] + bv.y);
            }
        }
    }
}

__global__ __launch_bounds__(256, 2) void gemm_qkv_kernel(
    const __half* __restrict__ X, const __half* __restrict__ Wt4,
    const float* __restrict__ bq, const float* __restrict__ bk,
    const float* __restrict__ bv,
    __half* __restrict__ Q, __half* __restrict__ K, __half* __restrict__ V)
{
    extern __shared__ __half smh[];
    const __half* W = Wt4 + (size_t)blockIdx.z * HIDDEN * HIDDEN;
    const float* b  = (blockIdx.z == 0) ? bq : (blockIdx.z == 1) ? bk : bv;
    __half*      C  = (blockIdx.z == 0) ? Q  : (blockIdx.z == 1) ? K  : V;
    gemm_body_f16<true>(X, W, b, C, smh);
}

__global__ __launch_bounds__(256, 2) void gemm_o_kernel(
    const __half* __restrict__ A, const __half* __restrict__ W,
    const float* __restrict__ b, float* __restrict__ C)
{
    extern __shared__ __half smh[];
    gemm_body_f16<false>(A, W, b, C, smh);
}

// ---------------------------------------------------------------------------
// Banded attention, fp16 MMA. Block = (chunk, head, batch), 8 warps (2x4).
// Phase A: Qs 64x72h [0,4608), Ks 192x72h [4608,18432) -- dead after sync.
// Phase B: Ph 64x200h [0,12800), Vs 192x72h [12800,26624).
// misc (floats) after half 26624: vld 192 | redM 256 | redS 256.
// Total 56064 bytes -> 2 blocks/SM (reg-limited).
// ---------------------------------------------------------------------------
#define QS_OFF   0
#define KS_OFF   4608
#define PH_OFF   0
#define PH_STRIDE 200
#define VS_OFF   12800
#define MISC_HALF 26624
#define ATTN_SMEM_BYTES (MISC_HALF * 2 + 704 * 4)   // 56064

__global__ __launch_bounds__(256) void attn_kernel(const float* __restrict__ maskp)
{
    extern __shared__ __half smh[];
    __half* Qs = smh + QS_OFF;
    __half* Ks = smh + KS_OFF;
    __half* Ph = smh + PH_OFF;
    __half* Vs = smh + VS_OFF;
    float* vld  = (float*)(smh + MISC_HALF);
    float* redM = vld + 192;
    float* redS = redM + 256;

    const int c = blockIdx.x;
    const int h = blockIdx.y;
    const int b = blockIdx.z;
    const int tid  = threadIdx.x;
    const int lane = tid & 31;
    const int wid  = tid >> 5;
    const int wm   = wid >> 2;
    const int wn   = wid & 3;
    const int qq   = lane >> 2;
    const int qk   = lane & 3;
    const int g    = lane >> 3;
    const int lr   = lane & 7;

    const size_t headoff = (size_t)h * HDIM;
    const size_t bbase   = (size_t)b * S_LEN;
    const int base = c * 64 - 64;

    const uint32_t sm_u = (uint32_t)__cvta_generic_to_shared(smh);

    // ---- load Q (64x64h) and K (192x64h): 16B chunks, stride 72 halves
#pragma unroll
    for (int it = 0; it < 2; it++) {
        int idx = tid + it * 256;          // 0..511
        int r = idx >> 3, cc = idx & 7;
        uint4 v = *(const uint4*)(g_Qh + (bbase + c * 64 + r) * HIDDEN + headoff + cc * 8);
        *(uint4*)(Qs + r * TSH + cc * 8) = v;
    }
#pragma unroll
    for (int it = 0; it < 6; it++) {
        int idx = tid + it * 256;          // 0..1535
        int r = idx >> 3, cc = idx & 7;
        int jg = base + r;
        uint4 v = make_uint4(0, 0, 0, 0);
        if (jg >= 0 && jg < S_LEN)
            v = *(const uint4*)(g_Kh + (bbase + jg) * HIDDEN + headoff + cc * 8);
        *(uint4*)(Ks + r * TSH + cc * 8) = v;
    }
    if (tid < 192) {
        int jg = base + tid;
        vld[tid] = (jg >= 0 && jg < S_LEN && maskp[b * S_LEN + jg] > 0.f) ? 1.f : 0.f;
    }
    __syncthreads();

    // ---- Phase A: S = Q K^T  (warp rows wm*32..+32, cols wn*48..+48, K=64)
    float acc[2][6][4];
#pragma unroll
    for (int mt = 0; mt < 2; mt++)
#pragma unroll
        for (int nt = 0; nt < 6; nt++)
#pragma unroll
            for (int t = 0; t < 4; t++) acc[mt][nt][t] = 0.f;

    {
        const uint32_t a_base = sm_u + (uint32_t)(QS_OFF * 2 +
                                (wm * 32 + (lane & 15)) * 144 + (lane >> 4) * 16);
        const uint32_t b_base = sm_u + (uint32_t)(KS_OFF * 2 +
                                (wn * 48 + (g >> 1) * 8 + lr) * 144 + (g & 1) * 16);
#pragma unroll
        for (int ks = 0; ks < 4; ks++) {
            const uint32_t kboff = (uint32_t)(ks * 32);
            uint32_t af[2][4];
#pragma unroll
            for (int mt = 0; mt < 2; mt++)
                ldsm_x4(af[mt], a_base + (uint32_t)(mt * 16 * 144) + kboff);
            uint32_t bf[3][4];
#pragma unroll
            for (int ntp = 0; ntp < 3; ntp++)
                ldsm_x4(bf[ntp], b_base + (uint32_t)(ntp * 16 * 144) + kboff);
#pragma unroll
            for (int mt = 0; mt < 2; mt++)
#pragma unroll
                for (int nt = 0; nt < 6; nt++)
                    mma_f16(acc[mt][nt], af[mt], &bf[nt >> 1][(nt & 1) * 2]);
        }
    }

    // ---- scale + band/valid mask + row-max partials
    float mrow[2][2];
#pragma unroll
    for (int mt = 0; mt < 2; mt++)
#pragma unroll
        for (int hf = 0; hf < 2; hf++) mrow[mt][hf] = -1e30f;

#pragma unroll
    for (int mt = 0; mt < 2; mt++)
#pragma unroll
        for (int nt = 0; nt < 6; nt++) {
            int colb = wn * 48 + nt * 8 + 2 * qk;
#pragma unroll
            for (int hf = 0; hf < 2; hf++) {
                int row = wm * 32 + mt * 16 + qq + 8 * hf;
#pragma unroll
                for (int e = 0; e < 2; e++) {
                    int col = colb + e;
                    float v = acc[mt][nt][hf * 2 + e] * 0.125f;
                    bool ok = (col >= row) && (col <= row + 128) && (vld[col] > 0.f);
                    v = ok ? v : -1e9f;
                    acc[mt][nt][hf * 2 + e] = v;
                    mrow[mt][hf] = fmaxf(mrow[mt][hf], v);
                }
            }
        }
#pragma unroll
    for (int mt = 0; mt < 2; mt++)
#pragma unroll
        for (int hf = 0; hf < 2; hf++) {
            float m = mrow[mt][hf];
            m = fmaxf(m, __shfl_xor_sync(0xffffffffu, m, 1));
            m = fmaxf(m, __shfl_xor_sync(0xffffffffu, m, 2));
            mrow[mt][hf] = m;
        }
    if (qk == 0) {
#pragma unroll
        for (int mt = 0; mt < 2; mt++)
#pragma unroll
            for (int hf = 0; hf < 2; hf++)
                redM[wn * 64 + wm * 32 + mt * 16 + qq + 8 * hf] = mrow[mt][hf];
    }
    __syncthreads();   // redM ready; all Qs/Ks reads done -> overlay safe

    // ---- global max, exp, fp16 P store (overlay), row sums; V load
    float gmv[2][2], srow[2][2];
#pragma unroll
    for (int mt = 0; mt < 2; mt++)
#pragma unroll
        for (int hf = 0; hf < 2; hf++) {
            int row = wm * 32 + mt * 16 + qq + 8 * hf;
            float m = fmaxf(fmaxf(redM[row], redM[64 + row]),
                            fmaxf(redM[128 + row], redM[192 + row]));
            gmv[mt][hf] = m;
            srow[mt][hf] = 0.f;
        }

#pragma unroll
    for (int mt = 0; mt < 2; mt++)
#pragma unroll
        for (int nt = 0; nt < 6; nt++) {
            int colb = wn * 48 + nt * 8 + 2 * qk;
#pragma unroll
            for (int hf = 0; hf < 2; hf++) {
                int row = wm * 32 + mt * 16 + qq + 8 * hf;
                float p0 = __expf(acc[mt][nt][hf * 2 + 0] - gmv[mt][hf]);
                float p1 = __expf(acc[mt][nt][hf * 2 + 1] - gmv[mt][hf]);
                __half h0 = __float2half_rn(p0);
                __half h1 = __float2half_rn(p1);
                srow[mt][hf] += __half2float(h0) + __half2float(h1);
                *(__half2*)(Ph + row * PH_STRIDE + colb) = __halves2half2(h0, h1);
            }
        }

#pragma unroll
    for (int mt = 0; mt < 2; mt++)
#pragma unroll
        for (int hf = 0; hf < 2; hf++) {
            float s = srow[mt][hf];
            s += __shfl_xor_sync(0xffffffffu, s, 1);
            s += __shfl_xor_sync(0xffffffffu, s, 2);
            srow[mt][hf] = s;
        }
    if (qk == 0) {
#pragma unroll
        for (int mt = 0; mt < 2; mt++)
#pragma unroll
            for (int hf = 0; hf < 2; hf++)
                redS[wn * 64 + wm * 32 + mt * 16 + qq + 8 * hf] = srow[mt][hf];
    }

    // V tile (fresh region, disjoint from Ph)
#pragma unroll
    for (int it = 0; it < 6; it++) {
        int idx = tid + it * 256;
        int r = idx >> 3, cc = idx & 7;
        int jg = base + r;
        uint4 v = make_uint4(0, 0, 0, 0);
        if (jg >= 0 && jg < S_LEN)
            v = *(const uint4*)(g_Vh + (bbase + jg) * HIDDEN + headoff + cc * 8);
        *(uint4*)(Vs + r * TSH + cc * 8) = v;
    }
    __syncthreads();   // Ph, redS, Vs ready

    // ---- Phase B: ctx = P V  (warp rows wm*32..+32, cols wn*16..+16, K=192)
    float c2[2][2][4];
#pragma unroll
    for (int mt = 0; mt < 2; mt++)
#pragma unroll
        for (int nt = 0; nt < 2; nt++)
#pragma unroll
            for (int t = 0; t < 4; t++) c2[mt][nt][t] = 0.f;

    {
        const uint32_t a_base = sm_u + (uint32_t)(PH_OFF * 2 +
                                (wm * 32 + (lane & 15)) * (PH_STRIDE * 2) + (lane >> 4) * 16);
        // trans-B: matrices [k0-7 n0-7][k8-15 n0-7][k0-7 n8-15][k8-15 n8-15]
        const uint32_t bt_base = sm_u + (uint32_t)(VS_OFF * 2 +
                                 ((g & 1) * 8 + lr) * 144 + (wn * 16 + (g >> 1) * 8) * 2);
#pragma unroll
        for (int ks = 0; ks < 12; ks++) {
            uint32_t af[2][4];
#pragma unroll
            for (int mt = 0; mt < 2; mt++)
                ldsm_x4(af[mt], a_base + (uint32_t)(mt * 16 * PH_STRIDE * 2 + ks * 32));
            uint32_t bf[4];
            ldsm_x4_t(bf, bt_base + (uint32_t)(ks * 16 * 144));
#pragma unroll
            for (int mt = 0; mt < 2; mt++)
#pragma unroll
                for (int nt = 0; nt < 2; nt++)
                    mma_f16(c2[mt][nt], af[mt], &bf[nt * 2]);
        }
    }

    // ---- epilogue: normalize, fp16 store to g_ctxh
#pragma unroll
    for (int mt = 0; mt < 2; mt++)
#pragma unroll
        for (int hf = 0; hf < 2; hf++) {
            int row = wm * 32 + mt * 16 + qq + 8 * hf;
            float s = redS[row] + redS[64 + row] + redS[128 + row] + redS[192 + row];
            float rinv = 1.f / s;
            __half* Og = g_ctxh + (bbase + c * 64 + row) * HIDDEN + headoff;
#pragma unroll
            for (int nt = 0; nt < 2; nt++) {
                int col = wn * 16 + nt * 8 + 2 * qk;
                *(__half2*)(Og + col) = __floats2half2_rn(c2[mt][nt][hf * 2 + 0] * rinv,
                                                          c2[mt][nt][hf * 2 + 1] * rinv);
            }
        }
}

// ---------------------------------------------------------------------------
extern "C" void kernel_launch(void* const* d_in, const int* in_sizes, int n_in,
                              void* d_out, int out_size)
{
    const float* X    = (const float*)d_in[0];
    const float* mask = (const float*)d_in[1];
    const float* Wq   = (const float*)d_in[2];
    const float* bq   = (const float*)d_in[3];
    const float* Wk   = (const float*)d_in[4];
    const float* bk   = (const float*)d_in[5];
    const float* Wv   = (const float*)d_in[6];
    const float* bv   = (const float*)d_in[7];
    const float* Wo   = (const float*)d_in[8];
    const float* bo   = (const float*)d_in[9];
    float* out = (float*)d_out;

    __half *qp, *kp, *vp, *cp, *xhp, *wtp;
    cudaGetSymbolAddress((void**)&qp, g_Qh);
    cudaGetSymbolAddress((void**)&kp, g_Kh);
    cudaGetSymbolAddress((void**)&vp, g_Vh);
    cudaGetSymbolAddress((void**)&cp, g_ctxh);
    cudaGetSymbolAddress((void**)&xhp, g_Xh);
    cudaGetSymbolAddress((void**)&wtp, g_Wth);
    __half* wt_o = wtp + 3 * (size_t)HIDDEN * HIDDEN;

    cudaFuncSetAttribute(attn_kernel, cudaFuncAttributeMaxDynamicSharedMemorySize,
                         ATTN_SMEM_BYTES);
    cudaFuncSetAttribute(gemm_qkv_kernel, cudaFuncAttributeMaxDynamicSharedMemorySize,
                         GEMM_SMEM_BYTES);
    cudaFuncSetAttribute(gemm_o_kernel, cudaFuncAttributeMaxDynamicSharedMemorySize,
                         GEMM_SMEM_BYTES);

    // ---- prepass: X -> fp16; weights -> fp16 transposed
    const int xN4 = MROWS * HIDDEN / 4;
    round_fp16_kernel<<<(xN4 + 255) / 256, 256>>>(X, xhp, xN4);
    dim3 tgrid(HIDDEN / 32, HIDDEN / 32, 4);
    round_transpose_kernel<<<tgrid, 256>>>(Wq, Wk, Wv, Wo, wtp);

    dim3 gblk(256);
    dim3 gqkv(HIDDEN / 128, MROWS / 128, 3);       // 8 x 64 x 3
    gemm_qkv_kernel<<<gqkv, gblk, GEMM_SMEM_BYTES>>>(xhp, wtp, bq, bk, bv, qp, kp, vp);

    dim3 agrid(NCHUNK, NHEAD, BATCH);
    attn_kernel<<<agrid, gblk, ATTN_SMEM_BYTES>>>(mask);

    dim3 go(HIDDEN / 128, MROWS / 128);            // 8 x 64
    gemm_o_kernel<<<go, gblk, GEMM_SMEM_BYTES>>>(cp, wt_o, bo, out);
}

// round 10
// speedup vs baseline: 2.1529x; 1.0554x over previous
#include <cuda_runtime.h>
#include <cuda_fp16.h>
#include <cstdint>

// ---------------------------------------------------------------------------
// LongformerAttention  B=2, S=4096, HID=1024, H=16, D=64, W=64
// Round 10: GEMM single-sync mainloop; attention all-cp.async loads with
// zfill + V prefetch overlapped with Phase A. fp16 mma.sync throughout.
// ---------------------------------------------------------------------------

#define S_LEN   4096
#define HIDDEN  1024
#define NHEAD   16
#define HDIM    64
#define NCHUNK  64
#define BATCH   2
#define MROWS   (BATCH * S_LEN)   // 8192

__device__ __half g_Qh[(size_t)MROWS * HIDDEN];
__device__ __half g_Kh[(size_t)MROWS * HIDDEN];
__device__ __half g_Vh[(size_t)MROWS * HIDDEN];
__device__ __half g_ctxh[(size_t)MROWS * HIDDEN];
__device__ __half g_Xh[(size_t)MROWS * HIDDEN];
__device__ __half g_Wth[4][(size_t)HIDDEN * HIDDEN];     // fp16 TRANSPOSED W [n][k]

__device__ __forceinline__ void mma_f16(float c[4], const uint32_t a[4], const uint32_t b[2]) {
    asm volatile(
        "mma.sync.aligned.m16n8k16.row.col.f32.f16.f16.f32 "
        "{%0,%1,%2,%3}, {%4,%5,%6,%7}, {%8,%9}, {%0,%1,%2,%3};"
        : "+f"(c[0]), "+f"(c[1]), "+f"(c[2]), "+f"(c[3])
        : "r"(a[0]), "r"(a[1]), "r"(a[2]), "r"(a[3]), "r"(b[0]), "r"(b[1]));
}

__device__ __forceinline__ void cp_async16(uint32_t dst, const void* src) {
    asm volatile("cp.async.cg.shared.global [%0], [%1], 16;\n"
                 :: "r"(dst), "l"(src));
}

// zfill variant: copies n bytes (n in {0,16}), zero-fills the rest of 16B
__device__ __forceinline__ void cp_async16z(uint32_t dst, const void* src, uint32_t n) {
    asm volatile("cp.async.cg.shared.global [%0], [%1], 16, %2;\n"
                 :: "r"(dst), "l"(src), "r"(n));
}

__device__ __forceinline__ void ldsm_x4(uint32_t r[4], uint32_t addr) {
    asm volatile("ldmatrix.sync.aligned.m8n8.x4.shared.b16 {%0,%1,%2,%3}, [%4];"
                 : "=r"(r[0]), "=r"(r[1]), "=r"(r[2]), "=r"(r[3]) : "r"(addr));
}

__device__ __forceinline__ void ldsm_x4_t(uint32_t r[4], uint32_t addr) {
    asm volatile("ldmatrix.sync.aligned.m8n8.x4.trans.shared.b16 {%0,%1,%2,%3}, [%4];"
                 : "=r"(r[0]), "=r"(r[1]), "=r"(r[2]), "=r"(r[3]) : "r"(addr));
}

// ---------------------------------------------------------------------------
// Prepass
// ---------------------------------------------------------------------------
__global__ __launch_bounds__(256) void round_fp16_kernel(
    const float* __restrict__ in, __half* __restrict__ out, int n4)
{
    int i = blockIdx.x * blockDim.x + threadIdx.x;
    if (i < n4) {
        float4 v = ((const float4*)in)[i];
        ((__half2*)out)[2 * i]     = __floats2half2_rn(v.x, v.y);
        ((__half2*)out)[2 * i + 1] = __floats2half2_rn(v.z, v.w);
    }
}

__global__ __launch_bounds__(256) void round_transpose_kernel(
    const float* __restrict__ w0, const float* __restrict__ w1,
    const float* __restrict__ w2, const float* __restrict__ w3,
    __half* __restrict__ out4)
{
    __shared__ float tile[32][33];
    const float* in = (blockIdx.z == 0) ? w0 : (blockIdx.z == 1) ? w1 :
                      (blockIdx.z == 2) ? w2 : w3;
    __half* out = out4 + (size_t)blockIdx.z * HIDDEN * HIDDEN;
    int k0 = blockIdx.x * 32, n0 = blockIdx.y * 32;
    int tx = threadIdx.x & 31, ty = threadIdx.x >> 5;
#pragma unroll
    for (int i = 0; i < 32; i += 8)
        tile[ty + i][tx] = in[(size_t)(k0 + ty + i) * HIDDEN + n0 + tx];
    __syncthreads();
#pragma unroll
    for (int i = 0; i < 32; i += 8)
        out[(size_t)(n0 + ty + i) * HIDDEN + k0 + tx] = __float2half_rn(tile[tx][ty + i]);
}

// ---------------------------------------------------------------------------
// fp16 GEMM: C[M,N] = A[M,K] @ Bt[N,K]^T + bias[N]
// Block 128x128, BK=64, 3-stage cp.async, single sync per iteration.
// ---------------------------------------------------------------------------
#define GK 1024
#define GN 1024
#define TSH 72
#define T_HALVES (128 * TSH)
#define STAGE_HALVES (2 * T_HALVES)
#define GEMM_SMEM_BYTES (3 * STAGE_HALVES * 2)  // 110592

template <bool OUT_HALF>
__device__ __forceinline__ void gemm_body_f16(
    const __half* __restrict__ A, const __half* __restrict__ Bt,
    const float* __restrict__ bias, void* __restrict__ Cv, __half* sm)
{
    const int tid  = threadIdx.x;
    const int lane = tid & 31;
    const int wid  = tid >> 5;
    const int wm   = wid >> 2;
    const int wn   = wid & 3;
    const int qq   = lane >> 2;
    const int qk   = lane & 3;
    const int brow = blockIdx.y * 128;
    const int bcol = blockIdx.x * 128;

    const int g  = lane >> 3;
    const int lr = lane & 7;

    const uint32_t sm_u = (uint32_t)__cvta_generic_to_shared(sm);

    float acc[4][4][4];
#pragma unroll
    for (int i = 0; i < 4; i++)
#pragma unroll
        for (int j = 0; j < 4; j++)
#pragma unroll
            for (int t = 0; t < 4; t++) acc[i][j][t] = 0.f;

    auto issue = [&](int slot, int k0) {
        uint32_t as_u = sm_u + (uint32_t)(slot * STAGE_HALVES) * 2u;
        uint32_t bs_u = as_u + (uint32_t)T_HALVES * 2u;
#pragma unroll
        for (int i = 0; i < 4; i++) {
            int idx = tid + i * 256;
            int r = idx >> 3, c = idx & 7;
            cp_async16(as_u + (uint32_t)(r * 144 + c * 16),
                       A + (size_t)(brow + r) * GK + k0 + c * 8);
        }
#pragma unroll
        for (int i = 0; i < 4; i++) {
            int idx = tid + i * 256;
            int r = idx >> 3, c = idx & 7;
            cp_async16(bs_u + (uint32_t)(r * 144 + c * 16),
                       Bt + (size_t)(bcol + r) * GK + k0 + c * 8);
        }
        asm volatile("cp.async.commit_group;\n" ::: "memory");
    };

    issue(0, 0);
    issue(1, 64);

    for (int t = 0; t < 16; t++) {
        if (t == 15)
            asm volatile("cp.async.wait_group 0;\n" ::: "memory");
        else
            asm volatile("cp.async.wait_group 1;\n" ::: "memory");
        __syncthreads();   // single barrier per iter: also orders last iter's
                           // reads of slot (t+2)%3 before the issue below (WAR)

        if (t + 2 < 16)
            issue((t + 2) % 3, (t + 2) * 64);

        const int slot = t % 3;
        const uint32_t as_u = sm_u + (uint32_t)(slot * STAGE_HALVES) * 2u;
        const uint32_t bs_u = as_u + (uint32_t)T_HALVES * 2u;
        const uint32_t a_base = as_u + (uint32_t)((wm * 64 + (lane & 15)) * 144 + (lane >> 4) * 16);
        const uint32_t b_base = bs_u + (uint32_t)((wn * 32 + (g >> 1) * 8 + lr) * 144 + (g & 1) * 16);

#pragma unroll
        for (int ks = 0; ks < 4; ks++) {
            const uint32_t kboff = (uint32_t)(ks * 32);
            uint32_t af[4][4];
#pragma unroll
            for (int mt = 0; mt < 4; mt++)
                ldsm_x4(af[mt], a_base + (uint32_t)(mt * 16 * 144) + kboff);
            uint32_t bf[2][4];
#pragma unroll
            for (int ntp = 0; ntp < 2; ntp++)
                ldsm_x4(bf[ntp], b_base + (uint32_t)(ntp * 16 * 144) + kboff);
#pragma unroll
            for (int mt = 0; mt < 4; mt++)
#pragma unroll
                for (int nt = 0; nt < 4; nt++)
                    mma_f16(acc[mt][nt], af[mt], &bf[nt >> 1][(nt & 1) * 2]);
        }
        // no trailing sync: next iteration's top barrier provides the ordering
    }

#pragma unroll
    for (int nt = 0; nt < 4; nt++) {
        int cc = bcol + wn * 32 + nt * 8 + 2 * qk;
        float2 bv = *(const float2*)(bias + cc);
#pragma unroll
        for (int mt = 0; mt < 4; mt++) {
            int r = brow + wm * 64 + mt * 16 + qq;
            if (OUT_HALF) {
                __half* C = (__half*)Cv;
                *(__half2*)(C + (size_t)r * GN + cc) =
                    __floats2half2_rn(acc[mt][nt][0] + bv.x, acc[mt][nt][1] + bv.y);
                *(__half2*)(C + (size_t)(r + 8) * GN + cc) =
                    __floats2half2_rn(acc[mt][nt][2] + bv.x, acc[mt][nt][3] + bv.y);
            } else {
                float* C = (float*)Cv;
                *(float2*)(C + (size_t)r * GN + cc) =
                    make_float2(acc[mt][nt][0] + bv.x, acc[mt][nt][1] + bv.y);
                *(float2*)(C + (size_t)(r + 8) * GN + cc) =
                    make_float2(acc[mt][nt][2] + bv.x, acc[mt][nt][3] + bv.y);
            }
        }
    }
}

__global__ __launch_bounds__(256, 2) void gemm_qkv_kernel(
    const __half* __restrict__ X, const __half* __restrict__ Wt4,
    const float* __restrict__ bq, const float* __restrict__ bk,
    const float* __restrict__ bv,
    __half* __restrict__ Q, __half* __restrict__ K, __half* __restrict__ V)
{
    extern __shared__ __half smh[];
    const __half* W = Wt4 + (size_t)blockIdx.z * HIDDEN * HIDDEN;
    const float* b  = (blockIdx.z == 0) ? bq : (blockIdx.z == 1) ? bk : bv;
    __half*      C  = (blockIdx.z == 0) ? Q  : (blockIdx.z == 1) ? K  : V;
    gemm_body_f16<true>(X, W, b, C, smh);
}

__global__ __launch_bounds__(256, 2) void gemm_o_kernel(
    const __half* __restrict__ A, const __half* __restrict__ W,
    const float* __restrict__ b, float* __restrict__ C)
{
    extern __shared__ __half smh[];
    gemm_body_f16<false>(A, W, b, C, smh);
}

// ---------------------------------------------------------------------------
// Banded attention, fp16 MMA, all-cp.async loads.
// Layout (halves): Qs [0,4608) 64x72 | Ks [4608,18432) 192x72 |
//                  Vs [18432,32256) 192x72 (own region, prefetched async) |
// Ph 64x200 overlays [0,12800) (Q+K dead after Phase A).
// misc floats after half 32256: vld 192 | redM 256 | redS 256.
// Total 67328 B -> 2 blocks/SM (reg-limited).
// cp.async groups: group0 = Q+K (waited before Phase A), group1 = V
// (waited only before Phase B -> V load fully overlapped with Phase A).
// ---------------------------------------------------------------------------
#define QS_OFF    0
#define KS_OFF    4608
#define VS_OFF    18432
#define PH_OFF    0
#define PH_STRIDE 200
#define MISC_HALF 32256
#define ATTN_SMEM_BYTES (MISC_HALF * 2 + 704 * 4)   // 67328

__global__ __launch_bounds__(256) void attn_kernel(const float* __restrict__ maskp)
{
    extern __shared__ __half smh[];
    __half* Ph = smh + PH_OFF;
    float* vld  = (float*)(smh + MISC_HALF);
    float* redM = vld + 192;
    float* redS = redM + 256;

    const int c = blockIdx.x;
    const int h = blockIdx.y;
    const int b = blockIdx.z;
    const int tid  = threadIdx.x;
    const int lane = tid & 31;
    const int wid  = tid >> 5;
    const int wm   = wid >> 2;
    const int wn   = wid & 3;
    const int qq   = lane >> 2;
    const int qk   = lane & 3;
    const int g    = lane >> 3;
    const int lr   = lane & 7;

    const size_t headoff = (size_t)h * HDIM;
    const size_t bbase   = (size_t)b * S_LEN;
    const int base = c * 64 - 64;

    const uint32_t sm_u = (uint32_t)__cvta_generic_to_shared(smh);
    const uint32_t qs_u = sm_u + QS_OFF * 2;
    const uint32_t ks_u = sm_u + KS_OFF * 2;
    const uint32_t vs_u = sm_u + VS_OFF * 2;

    // ---- group 0: Q (64x64h) + K (192x64h), 16B chunks, stride 144B
#pragma unroll
    for (int it = 0; it < 2; it++) {
        int idx = tid + it * 256;
        int r = idx >> 3, cc = idx & 7;
        cp_async16(qs_u + (uint32_t)(r * 144 + cc * 16),
                   g_Qh + (bbase + c * 64 + r) * HIDDEN + headoff + cc * 8);
    }
#pragma unroll
    for (int it = 0; it < 6; it++) {
        int idx = tid + it * 256;
        int r = idx >> 3, cc = idx & 7;
        int jg = base + r;
        bool ok = (jg >= 0) && (jg < S_LEN);
        int jc = ok ? jg : 0;
        cp_async16z(ks_u + (uint32_t)(r * 144 + cc * 16),
                    g_Kh + (bbase + jc) * HIDDEN + headoff + cc * 8, ok ? 16u : 0u);
    }
    asm volatile("cp.async.commit_group;\n" ::: "memory");

    // ---- group 1: V (192x64h) — consumed only in Phase B
#pragma unroll
    for (int it = 0; it < 6; it++) {
        int idx = tid + it * 256;
        int r = idx >> 3, cc = idx & 7;
        int jg = base + r;
        bool ok = (jg >= 0) && (jg < S_LEN);
        int jc = ok ? jg : 0;
        cp_async16z(vs_u + (uint32_t)(r * 144 + cc * 16),
                    g_Vh + (bbase + jc) * HIDDEN + headoff + cc * 8, ok ? 16u : 0u);
    }
    asm volatile("cp.async.commit_group;\n" ::: "memory");

    if (tid < 192) {
        int jg = base + tid;
        vld[tid] = (jg >= 0 && jg < S_LEN && maskp[b * S_LEN + jg] > 0.f) ? 1.f : 0.f;
    }

    asm volatile("cp.async.wait_group 1;\n" ::: "memory");   // Q+K landed
    __syncthreads();

    // ---- Phase A: S = Q K^T  (warp rows wm*32..+32, cols wn*48..+48, K=64)
    float acc[2][6][4];
#pragma unroll
    for (int mt = 0; mt < 2; mt++)
#pragma unroll
        for (int nt = 0; nt < 6; nt++)
#pragma unroll
            for (int t = 0; t < 4; t++) acc[mt][nt][t] = 0.f;

    {
        const uint32_t a_base = qs_u + (uint32_t)((wm * 32 + (lane & 15)) * 144 + (lane >> 4) * 16);
        const uint32_t b_base = ks_u + (uint32_t)((wn * 48 + (g >> 1) * 8 + lr) * 144 + (g & 1) * 16);
#pragma unroll
        for (int ks = 0; ks < 4; ks++) {
            const uint32_t kboff = (uint32_t)(ks * 32);
            uint32_t af[2][4];
#pragma unroll
            for (int mt = 0; mt < 2; mt++)
                ldsm_x4(af[mt], a_base + (uint32_t)(mt * 16 * 144) + kboff);
            uint32_t bf[3][4];
#pragma unroll
            for (int ntp = 0; ntp < 3; ntp++)
                ldsm_x4(bf[ntp], b_base + (uint32_t)(ntp * 16 * 144) + kboff);
#pragma unroll
            for (int mt = 0; mt < 2; mt++)
#pragma unroll
                for (int nt = 0; nt < 6; nt++)
                    mma_f16(acc[mt][nt], af[mt], &bf[nt >> 1][(nt & 1) * 2]);
        }
    }

    // ---- scale + band/valid mask + row-max partials
    float mrow[2][2];
#pragma unroll
    for (int mt = 0; mt < 2; mt++)
#pragma unroll
        for (int hf = 0; hf < 2; hf++) mrow[mt][hf] = -1e30f;

#pragma unroll
    for (int mt = 0; mt < 2; mt++)
#pragma unroll
        for (int nt = 0; nt < 6; nt++) {
            int colb = wn * 48 + nt * 8 + 2 * qk;
#pragma unroll
            for (int hf = 0; hf < 2; hf++) {
                int row = wm * 32 + mt * 16 + qq + 8 * hf;
#pragma unroll
                for (int e = 0; e < 2; e++) {
                    int col = colb + e;
                    float v = acc[mt][nt][hf * 2 + e] * 0.125f;
                    bool ok = (col >= row) && (col <= row + 128) && (vld[col] > 0.f);
                    v = ok ? v : -1e9f;
                    acc[mt][nt][hf * 2 + e] = v;
                    mrow[mt][hf] = fmaxf(mrow[mt][hf], v);
                }
            }
        }
#pragma unroll
    for (int mt = 0; mt < 2; mt++)
#pragma unroll
        for (int hf = 0; hf < 2; hf++) {
            float m = mrow[mt][hf];
            m = fmaxf(m, __shfl_xor_sync(0xffffffffu, m, 1));
            m = fmaxf(m, __shfl_xor_sync(0xffffffffu, m, 2));
            mrow[mt][hf] = m;
        }
    if (qk == 0) {
#pragma unroll
        for (int mt = 0; mt < 2; mt++)
#pragma unroll
            for (int hf = 0; hf < 2; hf++)
                redM[wn * 64 + wm * 32 + mt * 16 + qq + 8 * hf] = mrow[mt][hf];
    }
    __syncthreads();   // redM ready; all Q/K reads done -> P overlay safe

    // ---- global max, exp, fp16 P store (overlay), row sums
    float gmv[2][2], srow[2][2];
#pragma unroll
    for (int mt = 0; mt < 2; mt++)
#pragma unroll
        for (int hf = 0; hf < 2; hf++) {
            int row = wm * 32 + mt * 16 + qq + 8 * hf;
            float m = fmaxf(fmaxf(redM[row], redM[64 + row]),
                            fmaxf(redM[128 + row], redM[192 + row]));
            gmv[mt][hf] = m;
            srow[mt][hf] = 0.f;
        }

#pragma unroll
    for (int mt = 0; mt < 2; mt++)
#pragma unroll
        for (int nt = 0; nt < 6; nt++) {
            int colb = wn * 48 + nt * 8 + 2 * qk;
#pragma unroll
            for (int hf = 0; hf < 2; hf++) {
                int row = wm * 32 + mt * 16 + qq + 8 * hf;
                float p0 = __expf(acc[mt][nt][hf * 2 + 0] - gmv[mt][hf]);
                float p1 = __expf(acc[mt][nt][hf * 2 + 1] - gmv[mt][hf]);
                __half h0 = __float2half_rn(p0);
                __half h1 = __float2half_rn(p1);
                srow[mt][hf] += __half2float(h0) + __half2float(h1);
                *(__half2*)(Ph + row * PH_STRIDE + colb) = __halves2half2(h0, h1);
            }
        }

#pragma unroll
    for (int mt = 0; mt < 2; mt++)
#pragma unroll
        for (int hf = 0; hf < 2; hf++) {
            float s = srow[mt][hf];
            s += __shfl_xor_sync(0xffffffffu, s, 1);
            s += __shfl_xor_sync(0xffffffffu, s, 2);
            srow[mt][hf] = s;
        }
    if (qk == 0) {
#pragma unroll
        for (int mt = 0; mt < 2; mt++)
#pragma unroll
            for (int hf = 0; hf < 2; hf++)
                redS[wn * 64 + wm * 32 + mt * 16 + qq + 8 * hf] = srow[mt][hf];
    }

    asm volatile("cp.async.wait_group 0;\n" ::: "memory");   // V landed (long ago)
    __syncthreads();   // Ph, redS, Vs all visible

    // ---- Phase B: ctx = P V  (warp rows wm*32..+32, cols wn*16..+16, K=192)
    float c2[2][2][4];
#pragma unroll
    for (int mt = 0; mt < 2; mt++)
#pragma unroll
        for (int nt = 0; nt < 2; nt++)
#pragma unroll
            for (int t = 0; t < 4; t++) c2[mt][nt][t] = 0.f;

    {
        const uint32_t a_base = sm_u + (uint32_t)(PH_OFF * 2 +
                                (wm * 32 + (lane & 15)) * (PH_STRIDE * 2) + (lane >> 4) * 16);
        const uint32_t bt_base = vs_u + (uint32_t)(((g & 1) * 8 + lr) * 144 +
                                 (wn * 16 + (g >> 1) * 8) * 2);
#pragma unroll
        for (int ks = 0; ks < 12; ks++) {
            uint32_t af[2][4];
#pragma unroll
            for (int mt = 0; mt < 2; mt++)
                ldsm_x4(af[mt], a_base + (uint32_t)(mt * 16 * PH_STRIDE * 2 + ks * 32));
            uint32_t bf[4];
            ldsm_x4_t(bf, bt_base + (uint32_t)(ks * 16 * 144));
#pragma unroll
            for (int mt = 0; mt < 2; mt++)
#pragma unroll
                for (int nt = 0; nt < 2; nt++)
                    mma_f16(c2[mt][nt], af[mt], &bf[nt * 2]);
        }
    }

    // ---- epilogue: normalize, fp16 store to g_ctxh
#pragma unroll
    for (int mt = 0; mt < 2; mt++)
#pragma unroll
        for (int hf = 0; hf < 2; hf++) {
            int row = wm * 32 + mt * 16 + qq + 8 * hf;
            float s = redS[row] + redS[64 + row] + redS[128 + row] + redS[192 + row];
            float rinv = 1.f / s;
            __half* Og = g_ctxh + (bbase + c * 64 + row) * HIDDEN + headoff;
#pragma unroll
            for (int nt = 0; nt < 2; nt++) {
                int col = wn * 16 + nt * 8 + 2 * qk;
                *(__half2*)(Og + col) = __floats2half2_rn(c2[mt][nt][hf * 2 + 0] * rinv,
                                                          c2[mt][nt][hf * 2 + 1] * rinv);
            }
        }
}

// ---------------------------------------------------------------------------
extern "C" void kernel_launch(void* const* d_in, const int* in_sizes, int n_in,
                              void* d_out, int out_size)
{
    const float* X    = (const float*)d_in[0];
    const float* mask = (const float*)d_in[1];
    const float* Wq   = (const float*)d_in[2];
    const float* bq   = (const float*)d_in[3];
    const float* Wk   = (const float*)d_in[4];
    const float* bk   = (const float*)d_in[5];
    const float* Wv   = (const float*)d_in[6];
    const float* bv   = (const float*)d_in[7];
    const float* Wo   = (const float*)d_in[8];
    const float* bo   = (const float*)d_in[9];
    float* out = (float*)d_out;

    __half *qp, *kp, *vp, *cp, *xhp, *wtp;
    cudaGetSymbolAddress((void**)&qp, g_Qh);
    cudaGetSymbolAddress((void**)&kp, g_Kh);
    cudaGetSymbolAddress((void**)&vp, g_Vh);
    cudaGetSymbolAddress((void**)&cp, g_ctxh);
    cudaGetSymbolAddress((void**)&xhp, g_Xh);
    cudaGetSymbolAddress((void**)&wtp, g_Wth);
    __half* wt_o = wtp + 3 * (size_t)HIDDEN * HIDDEN;

    cudaFuncSetAttribute(attn_kernel, cudaFuncAttributeMaxDynamicSharedMemorySize,
                         ATTN_SMEM_BYTES);
    cudaFuncSetAttribute(gemm_qkv_kernel, cudaFuncAttributeMaxDynamicSharedMemorySize,
                         GEMM_SMEM_BYTES);
    cudaFuncSetAttribute(gemm_o_kernel, cudaFuncAttributeMaxDynamicSharedMemorySize,
                         GEMM_SMEM_BYTES);

    const int xN4 = MROWS * HIDDEN / 4;
    round_fp16_kernel<<<(xN4 + 255) / 256, 256>>>(X, xhp, xN4);
    dim3 tgrid(HIDDEN / 32, HIDDEN / 32, 4);
    round_transpose_kernel<<<tgrid, 256>>>(Wq, Wk, Wv, Wo, wtp);

    dim3 gblk(256);
    dim3 gqkv(HIDDEN / 128, MROWS / 128, 3);       // 8 x 64 x 3
    gemm_qkv_kernel<<<gqkv, gblk, GEMM_SMEM_BYTES>>>(xhp, wtp, bq, bk, bv, qp, kp, vp);

    dim3 agrid(NCHUNK, NHEAD, BATCH);
    attn_kernel<<<agrid, gblk, ATTN_SMEM_BYTES>>>(mask);

    dim3 go(HIDDEN / 128, MROWS / 128);            // 8 x 64
    gemm_o_kernel<<<go, gblk, GEMM_SMEM_BYTES>>>(cp, wt_o, bo, out);
}

// round 11
// speedup vs baseline: 2.4537x; 1.1398x over previous
#include <cuda_runtime.h>
#include <cuda_fp16.h>
#include <cstdint>

// ---------------------------------------------------------------------------
// LongformerAttention  B=2, S=4096, HID=1024, H=16, D=64, W=64
// Round 11: fully-unrolled GEMM mainloop (constant smem slots, cross-iter
// scheduling) + merged prepass. fp16 mma.sync throughout.
// ---------------------------------------------------------------------------

#define S_LEN   4096
#define HIDDEN  1024
#define NHEAD   16
#define HDIM    64
#define NCHUNK  64
#define BATCH   2
#define MROWS   (BATCH * S_LEN)   // 8192

__device__ __half g_Qh[(size_t)MROWS * HIDDEN];
__device__ __half g_Kh[(size_t)MROWS * HIDDEN];
__device__ __half g_Vh[(size_t)MROWS * HIDDEN];
__device__ __half g_ctxh[(size_t)MROWS * HIDDEN];
__device__ __half g_Xh[(size_t)MROWS * HIDDEN];
__device__ __half g_Wth[4][(size_t)HIDDEN * HIDDEN];     // fp16 TRANSPOSED W [n][k]

__device__ __forceinline__ void mma_f16(float c[4], const uint32_t a[4], const uint32_t b[2]) {
    asm volatile(
        "mma.sync.aligned.m16n8k16.row.col.f32.f16.f16.f32 "
        "{%0,%1,%2,%3}, {%4,%5,%6,%7}, {%8,%9}, {%0,%1,%2,%3};"
        : "+f"(c[0]), "+f"(c[1]), "+f"(c[2]), "+f"(c[3])
        : "r"(a[0]), "r"(a[1]), "r"(a[2]), "r"(a[3]), "r"(b[0]), "r"(b[1]));
}

__device__ __forceinline__ void cp_async16(uint32_t dst, const void* src) {
    asm volatile("cp.async.cg.shared.global [%0], [%1], 16;\n"
                 :: "r"(dst), "l"(src));
}

__device__ __forceinline__ void cp_async16z(uint32_t dst, const void* src, uint32_t n) {
    asm volatile("cp.async.cg.shared.global [%0], [%1], 16, %2;\n"
                 :: "r"(dst), "l"(src), "r"(n));
}

__device__ __forceinline__ void ldsm_x4(uint32_t r[4], uint32_t addr) {
    asm volatile("ldmatrix.sync.aligned.m8n8.x4.shared.b16 {%0,%1,%2,%3}, [%4];"
                 : "=r"(r[0]), "=r"(r[1]), "=r"(r[2]), "=r"(r[3]) : "r"(addr));
}

__device__ __forceinline__ void ldsm_x4_t(uint32_t r[4], uint32_t addr) {
    asm volatile("ldmatrix.sync.aligned.m8n8.x4.trans.shared.b16 {%0,%1,%2,%3}, [%4];"
                 : "=r"(r[0]), "=r"(r[1]), "=r"(r[2]), "=r"(r[3]) : "r"(addr));
}

// ---------------------------------------------------------------------------
// Merged prepass: z=0..3 -> transpose+convert W[z]; z=4,5 -> convert X half
// ---------------------------------------------------------------------------
__global__ __launch_bounds__(256) void prepass_kernel(
    const float* __restrict__ X,
    const float* __restrict__ w0, const float* __restrict__ w1,
    const float* __restrict__ w2, const float* __restrict__ w3,
    __half* __restrict__ Xh, __half* __restrict__ out4)
{
    const int z = blockIdx.z;
    if (z < 4) {
        __shared__ float tile[32][33];
        const float* in = (z == 0) ? w0 : (z == 1) ? w1 : (z == 2) ? w2 : w3;
        __half* out = out4 + (size_t)z * HIDDEN * HIDDEN;
        int k0 = blockIdx.x * 32, n0 = blockIdx.y * 32;
        int tx = threadIdx.x & 31, ty = threadIdx.x >> 5;
#pragma unroll
        for (int i = 0; i < 32; i += 8)
            tile[ty + i][tx] = in[(size_t)(k0 + ty + i) * HIDDEN + n0 + tx];
        __syncthreads();
#pragma unroll
        for (int i = 0; i < 32; i += 8)
            out[(size_t)(n0 + ty + i) * HIDDEN + k0 + tx] = __float2half_rn(tile[tx][ty + i]);
    } else {
        // X convert: 2 z-slices x 1024 xy-blocks x 256 threads x 4 float4
        int blk = (z - 4) * 1024 + blockIdx.y * 32 + blockIdx.x;   // 0..2047
#pragma unroll
        for (int i = 0; i < 4; i++) {
            int idx = (blk * 4 + i) * 256 + threadIdx.x;           // 0..2097151
            float4 v = ((const float4*)X)[idx];
            ((__half2*)Xh)[2 * idx]     = __floats2half2_rn(v.x, v.y);
            ((__half2*)Xh)[2 * idx + 1] = __floats2half2_rn(v.z, v.w);
        }
    }
}

// ---------------------------------------------------------------------------
// fp16 GEMM: C[M,N] = A[M,K] @ Bt[N,K]^T + bias[N]
// Block 128x128, BK=64, 3-stage cp.async, fully unrolled mainloop.
// ---------------------------------------------------------------------------
#define GK 1024
#define GN 1024
#define TSH 72
#define T_HALVES (128 * TSH)
#define STAGE_HALVES (2 * T_HALVES)
#define GEMM_SMEM_BYTES (3 * STAGE_HALVES * 2)  // 110592

template <bool OUT_HALF>
__device__ __forceinline__ void gemm_body_f16(
    const __half* __restrict__ A, const __half* __restrict__ Bt,
    const float* __restrict__ bias, void* __restrict__ Cv, __half* sm)
{
    const int tid  = threadIdx.x;
    const int lane = tid & 31;
    const int wid  = tid >> 5;
    const int wm   = wid >> 2;
    const int wn   = wid & 3;
    const int qq   = lane >> 2;
    const int qk   = lane & 3;
    const int brow = blockIdx.y * 128;
    const int bcol = blockIdx.x * 128;

    const int g  = lane >> 3;
    const int lr = lane & 7;

    const uint32_t sm_u = (uint32_t)__cvta_generic_to_shared(sm);

    float acc[4][4][4];
#pragma unroll
    for (int i = 0; i < 4; i++)
#pragma unroll
        for (int j = 0; j < 4; j++)
#pragma unroll
            for (int t = 0; t < 4; t++) acc[i][j][t] = 0.f;

    const int ld_r = tid >> 3;             // 0..31 (+32*i)
    const int ld_c = tid & 7;
    const __half* Ag = A + (size_t)(brow + ld_r) * GK + ld_c * 8;
    const __half* Bg = Bt + (size_t)(bcol + ld_r) * GK + ld_c * 8;
    const uint32_t st_off = (uint32_t)(ld_r * 144 + ld_c * 16);

    auto issue = [&](int slot, int k0) {
        uint32_t as_u = sm_u + (uint32_t)(slot * STAGE_HALVES) * 2u + st_off;
        uint32_t bs_u = as_u + (uint32_t)T_HALVES * 2u;
#pragma unroll
        for (int i = 0; i < 4; i++)
            cp_async16(as_u + (uint32_t)(i * 32 * 144), Ag + (size_t)(i * 32) * GK + k0);
#pragma unroll
        for (int i = 0; i < 4; i++)
            cp_async16(bs_u + (uint32_t)(i * 32 * 144), Bg + (size_t)(i * 32) * GK + k0);
        asm volatile("cp.async.commit_group;\n" ::: "memory");
    };

    issue(0, 0);
    issue(1, 64);

    const uint32_t a_off = (uint32_t)((wm * 64 + (lane & 15)) * 144 + (lane >> 4) * 16);
    const uint32_t b_off = (uint32_t)T_HALVES * 2u +
                           (uint32_t)((wn * 32 + (g >> 1) * 8 + lr) * 144 + (g & 1) * 16);

#pragma unroll
    for (int t = 0; t < 16; t++) {
        if (t == 15)
            asm volatile("cp.async.wait_group 0;\n" ::: "memory");
        else
            asm volatile("cp.async.wait_group 1;\n" ::: "memory");
        __syncthreads();

        if (t + 2 < 16)
            issue((t + 2) % 3, (t + 2) * 64);

        const uint32_t base = sm_u + (uint32_t)((t % 3) * STAGE_HALVES) * 2u;
        const uint32_t a_base = base + a_off;
        const uint32_t b_base = base + b_off;

#pragma unroll
        for (int ks = 0; ks < 4; ks++) {
            const uint32_t kboff = (uint32_t)(ks * 32);
            uint32_t af[4][4];
#pragma unroll
            for (int mt = 0; mt < 4; mt++)
                ldsm_x4(af[mt], a_base + (uint32_t)(mt * 16 * 144) + kboff);
            uint32_t bf[2][4];
#pragma unroll
            for (int ntp = 0; ntp < 2; ntp++)
                ldsm_x4(bf[ntp], b_base + (uint32_t)(ntp * 16 * 144) + kboff);
#pragma unroll
            for (int mt = 0; mt < 4; mt++)
#pragma unroll
                for (int nt = 0; nt < 4; nt++)
                    mma_f16(acc[mt][nt], af[mt], &bf[nt >> 1][(nt & 1) * 2]);
        }
    }

#pragma unroll
    for (int nt = 0; nt < 4; nt++) {
        int cc = bcol + wn * 32 + nt * 8 + 2 * qk;
        float2 bv = *(const float2*)(bias + cc);
#pragma unroll
        for (int mt = 0; mt < 4; mt++) {
            int r = brow + wm * 64 + mt * 16 + qq;
            if (OUT_HALF) {
                __half* C = (__half*)Cv;
                *(__half2*)(C + (size_t)r * GN + cc) =
                    __floats2half2_rn(acc[mt][nt][0] + bv.x, acc[mt][nt][1] + bv.y);
                *(__half2*)(C + (size_t)(r + 8) * GN + cc) =
                    __floats2half2_rn(acc[mt][nt][2] + bv.x, acc[mt][nt][3] + bv.y);
            } else {
                float* C = (float*)Cv;
                *(float2*)(C + (size_t)r * GN + cc) =
                    make_float2(acc[mt][nt][0] + bv.x, acc[mt][nt][1] + bv.y);
                *(float2*)(C + (size_t)(r + 8) * GN + cc) =
                    make_float2(acc[mt][nt][2] + bv.x, acc[mt][nt][3] + bv.y);
            }
        }
    }
}

__global__ __launch_bounds__(256, 2) void gemm_qkv_kernel(
    const __half* __restrict__ X, const __half* __restrict__ Wt4,
    const float* __restrict__ bq, const float* __restrict__ bk,
    const float* __restrict__ bv,
    __half* __restrict__ Q, __half* __restrict__ K, __half* __restrict__ V)
{
    extern __shared__ __half smh[];
    const __half* W = Wt4 + (size_t)blockIdx.z * HIDDEN * HIDDEN;
    const float* b  = (blockIdx.z == 0) ? bq : (blockIdx.z == 1) ? bk : bv;
    __half*      C  = (blockIdx.z == 0) ? Q  : (blockIdx.z == 1) ? K  : V;
    gemm_body_f16<true>(X, W, b, C, smh);
}

__global__ __launch_bounds__(256, 2) void gemm_o_kernel(
    const __half* __restrict__ A, const __half* __restrict__ W,
    const float* __restrict__ b, float* __restrict__ C)
{
    extern __shared__ __half smh[];
    gemm_body_f16<false>(A, W, b, C, smh);
}

// ---------------------------------------------------------------------------
// Banded attention (unchanged from R10): fp16 MMA, all-cp.async, V prefetch.
// ---------------------------------------------------------------------------
#define QS_OFF    0
#define KS_OFF    4608
#define VS_OFF    18432
#define PH_OFF    0
#define PH_STRIDE 200
#define MISC_HALF 32256
#define ATTN_SMEM_BYTES (MISC_HALF * 2 + 704 * 4)   // 67328

__global__ __launch_bounds__(256) void attn_kernel(const float* __restrict__ maskp)
{
    extern __shared__ __half smh[];
    __half* Ph = smh + PH_OFF;
    float* vld  = (float*)(smh + MISC_HALF);
    float* redM = vld + 192;
    float* redS = redM + 256;

    const int c = blockIdx.x;
    const int h = blockIdx.y;
    const int b = blockIdx.z;
    const int tid  = threadIdx.x;
    const int lane = tid & 31;
    const int wid  = tid >> 5;
    const int wm   = wid >> 2;
    const int wn   = wid & 3;
    const int qq   = lane >> 2;
    const int qk   = lane & 3;
    const int g    = lane >> 3;
    const int lr   = lane & 7;

    const size_t headoff = (size_t)h * HDIM;
    const size_t bbase   = (size_t)b * S_LEN;
    const int base = c * 64 - 64;

    const uint32_t sm_u = (uint32_t)__cvta_generic_to_shared(smh);
    const uint32_t qs_u = sm_u + QS_OFF * 2;
    const uint32_t ks_u = sm_u + KS_OFF * 2;
    const uint32_t vs_u = sm_u + VS_OFF * 2;

#pragma unroll
    for (int it = 0; it < 2; it++) {
        int idx = tid + it * 256;
        int r = idx >> 3, cc = idx & 7;
        cp_async16(qs_u + (uint32_t)(r * 144 + cc * 16),
                   g_Qh + (bbase + c * 64 + r) * HIDDEN + headoff + cc * 8);
    }
#pragma unroll
    for (int it = 0; it < 6; it++) {
        int idx = tid + it * 256;
        int r = idx >> 3, cc = idx & 7;
        int jg = base + r;
        bool ok = (jg >= 0) && (jg < S_LEN);
        int jc = ok ? jg : 0;
        cp_async16z(ks_u + (uint32_t)(r * 144 + cc * 16),
                    g_Kh + (bbase + jc) * HIDDEN + headoff + cc * 8, ok ? 16u : 0u);
    }
    asm volatile("cp.async.commit_group;\n" ::: "memory");

#pragma unroll
    for (int it = 0; it < 6; it++) {
        int idx = tid + it * 256;
        int r = idx >> 3, cc = idx & 7;
        int jg = base + r;
        bool ok = (jg >= 0) && (jg < S_LEN);
        int jc = ok ? jg : 0;
        cp_async16z(vs_u + (uint32_t)(r * 144 + cc * 16),
                    g_Vh + (bbase + jc) * HIDDEN + headoff + cc * 8, ok ? 16u : 0u);
    }
    asm volatile("cp.async.commit_group;\n" ::: "memory");

    if (tid < 192) {
        int jg = base + tid;
        vld[tid] = (jg >= 0 && jg < S_LEN && maskp[b * S_LEN + jg] > 0.f) ? 1.f : 0.f;
    }

    asm volatile("cp.async.wait_group 1;\n" ::: "memory");
    __syncthreads();

    // ---- Phase A: S = Q K^T
    float acc[2][6][4];
#pragma unroll
    for (int mt = 0; mt < 2; mt++)
#pragma unroll
        for (int nt = 0; nt < 6; nt++)
#pragma unroll
            for (int t = 0; t < 4; t++) acc[mt][nt][t] = 0.f;

    {
        const uint32_t a_base = qs_u + (uint32_t)((wm * 32 + (lane & 15)) * 144 + (lane >> 4) * 16);
        const uint32_t b_base = ks_u + (uint32_t)((wn * 48 + (g >> 1) * 8 + lr) * 144 + (g & 1) * 16);
#pragma unroll
        for (int ks = 0; ks < 4; ks++) {
            const uint32_t kboff = (uint32_t)(ks * 32);
            uint32_t af[2][4];
#pragma unroll
            for (int mt = 0; mt < 2; mt++)
                ldsm_x4(af[mt], a_base + (uint32_t)(mt * 16 * 144) + kboff);
            uint32_t bf[3][4];
#pragma unroll
            for (int ntp = 0; ntp < 3; ntp++)
                ldsm_x4(bf[ntp], b_base + (uint32_t)(ntp * 16 * 144) + kboff);
#pragma unroll
            for (int mt = 0; mt < 2; mt++)
#pragma unroll
                for (int nt = 0; nt < 6; nt++)
                    mma_f16(acc[mt][nt], af[mt], &bf[nt >> 1][(nt & 1) * 2]);
        }
    }

    // ---- scale + band/valid mask + row-max partials
    float mrow[2][2];
#pragma unroll
    for (int mt = 0; mt < 2; mt++)
#pragma unroll
        for (int hf = 0; hf < 2; hf++) mrow[mt][hf] = -1e30f;

#pragma unroll
    for (int mt = 0; mt < 2; mt++)
#pragma unroll
        for (int nt = 0; nt < 6; nt++) {
            int colb = wn * 48 + nt * 8 + 2 * qk;
#pragma unroll
            for (int hf = 0; hf < 2; hf++) {
                int row = wm * 32 + mt * 16 + qq + 8 * hf;
#pragma unroll
                for (int e = 0; e < 2; e++) {
                    int col = colb + e;
                    float v = acc[mt][nt][hf * 2 + e] * 0.125f;
                    bool ok = (col >= row) && (col <= row + 128) && (vld[col] > 0.f);
                    v = ok ? v : -1e9f;
                    acc[mt][nt][hf * 2 + e] = v;
                    mrow[mt][hf] = fmaxf(mrow[mt][hf], v);
                }
            }
        }
#pragma unroll
    for (int mt = 0; mt < 2; mt++)
#pragma unroll
        for (int hf = 0; hf < 2; hf++) {
            float m = mrow[mt][hf];
            m = fmaxf(m, __shfl_xor_sync(0xffffffffu, m, 1));
            m = fmaxf(m, __shfl_xor_sync(0xffffffffu, m, 2));
            mrow[mt][hf] = m;
        }
    if (qk == 0) {
#pragma unroll
        for (int mt = 0; mt < 2; mt++)
#pragma unroll
            for (int hf = 0; hf < 2; hf++)
                redM[wn * 64 + wm * 32 + mt * 16 + qq + 8 * hf] = mrow[mt][hf];
    }
    __syncthreads();

    // ---- global max, exp, fp16 P store (overlay), row sums
    float gmv[2][2], srow[2][2];
#pragma unroll
    for (int mt = 0; mt < 2; mt++)
#pragma unroll
        for (int hf = 0; hf < 2; hf++) {
            int row = wm * 32 + mt * 16 + qq + 8 * hf;
            float m = fmaxf(fmaxf(redM[row], redM[64 + row]),
                            fmaxf(redM[128 + row], redM[192 + row]));
            gmv[mt][hf] = m;
            srow[mt][hf] = 0.f;
        }

#pragma unroll
    for (int mt = 0; mt < 2; mt++)
#pragma unroll
        for (int nt = 0; nt < 6; nt++) {
            int colb = wn * 48 + nt * 8 + 2 * qk;
#pragma unroll
            for (int hf = 0; hf < 2; hf++) {
                int row = wm * 32 + mt * 16 + qq + 8 * hf;
                float p0 = __expf(acc[mt][nt][hf * 2 + 0] - gmv[mt][hf]);
                float p1 = __expf(acc[mt][nt][hf * 2 + 1] - gmv[mt][hf]);
                __half h0 = __float2half_rn(p0);
                __half h1 = __float2half_rn(p1);
                srow[mt][hf] += __half2float(h0) + __half2float(h1);
                *(__half2*)(Ph + row * PH_STRIDE + colb) = __halves2half2(h0, h1);
            }
        }

#pragma unroll
    for (int mt = 0; mt < 2; mt++)
#pragma unroll
        for (int hf = 0; hf < 2; hf++) {
            float s = srow[mt][hf];
            s += __shfl_xor_sync(0xffffffffu, s, 1);
            s += __shfl_xor_sync(0xffffffffu, s, 2);
            srow[mt][hf] = s;
        }
    if (qk == 0) {
#pragma unroll
        for (int mt = 0; mt < 2; mt++)
#pragma unroll
            for (int hf = 0; hf < 2; hf++)
                redS[wn * 64 + wm * 32 + mt * 16 + qq + 8 * hf] = srow[mt][hf];
    }

    asm volatile("cp.async.wait_group 0;\n" ::: "memory");
    __syncthreads();

    // ---- Phase B: ctx = P V
    float c2[2][2][4];
#pragma unroll
    for (int mt = 0; mt < 2; mt++)
#pragma unroll
        for (int nt = 0; nt < 2; nt++)
#pragma unroll
            for (int t = 0; t < 4; t++) c2[mt][nt][t] = 0.f;

    {
        const uint32_t a_base = sm_u + (uint32_t)(PH_OFF * 2 +
                                (wm * 32 + (lane & 15)) * (PH_STRIDE * 2) + (lane >> 4) * 16);
        const uint32_t bt_base = vs_u + (uint32_t)(((g & 1) * 8 + lr) * 144 +
                                 (wn * 16 + (g >> 1) * 8) * 2);
#pragma unroll
        for (int ks = 0; ks < 12; ks++) {
            uint32_t af[2][4];
#pragma unroll
            for (int mt = 0; mt < 2; mt++)
                ldsm_x4(af[mt], a_base + (uint32_t)(mt * 16 * PH_STRIDE * 2 + ks * 32));
            uint32_t bf[4];
            ldsm_x4_t(bf, bt_base + (uint32_t)(ks * 16 * 144));
#pragma unroll
            for (int mt = 0; mt < 2; mt++)
#pragma unroll
                for (int nt = 0; nt < 2; nt++)
                    mma_f16(c2[mt][nt], af[mt], &bf[nt * 2]);
        }
    }

    // ---- epilogue
#pragma unroll
    for (int mt = 0; mt < 2; mt++)
#pragma unroll
        for (int hf = 0; hf < 2; hf++) {
            int row = wm * 32 + mt * 16 + qq + 8 * hf;
            float s = redS[row] + redS[64 + row] + redS[128 + row] + redS[192 + row];
            float rinv = 1.f / s;
            __half* Og = g_ctxh + (bbase + c * 64 + row) * HIDDEN + headoff;
#pragma unroll
            for (int nt = 0; nt < 2; nt++) {
                int col = wn * 16 + nt * 8 + 2 * qk;
                *(__half2*)(Og + col) = __floats2half2_rn(c2[mt][nt][hf * 2 + 0] * rinv,
                                                          c2[mt][nt][hf * 2 + 1] * rinv);
            }
        }
}

// ---------------------------------------------------------------------------
extern "C" void kernel_launch(void* const* d_in, const int* in_sizes, int n_in,
                              void* d_out, int out_size)
{
    const float* X    = (const float*)d_in[0];
    const float* mask = (const float*)d_in[1];
    const float* Wq   = (const float*)d_in[2];
    const float* bq   = (const float*)d_in[3];
    const float* Wk   = (const float*)d_in[4];
    const float* bk   = (const float*)d_in[5];
    const float* Wv   = (const float*)d_in[6];
    const float* bv   = (const float*)d_in[7];
    const float* Wo   = (const float*)d_in[8];
    const float* bo   = (const float*)d_in[9];
    float* out = (float*)d_out;

    __half *qp, *kp, *vp, *cp, *xhp, *wtp;
    cudaGetSymbolAddress((void**)&qp, g_Qh);
    cudaGetSymbolAddress((void**)&kp, g_Kh);
    cudaGetSymbolAddress((void**)&vp, g_Vh);
    cudaGetSymbolAddress((void**)&cp, g_ctxh);
    cudaGetSymbolAddress((void**)&xhp, g_Xh);
    cudaGetSymbolAddress((void**)&wtp, g_Wth);
    __half* wt_o = wtp + 3 * (size_t)HIDDEN * HIDDEN;

    cudaFuncSetAttribute(attn_kernel, cudaFuncAttributeMaxDynamicSharedMemorySize,
                         ATTN_SMEM_BYTES);
    cudaFuncSetAttribute(gemm_qkv_kernel, cudaFuncAttributeMaxDynamicSharedMemorySize,
                         GEMM_SMEM_BYTES);
    cudaFuncSetAttribute(gemm_o_kernel, cudaFuncAttributeMaxDynamicSharedMemorySize,
                         GEMM_SMEM_BYTES);

    // merged prepass: z 0..3 = W transpose, z 4..5 = X convert
    dim3 pgrid(32, 32, 6);
    prepass_kernel<<<pgrid, 256>>>(X, Wq, Wk, Wv, Wo, xhp, wtp);

    dim3 gblk(256);
    dim3 gqkv(HIDDEN / 128, MROWS / 128, 3);       // 8 x 64 x 3
    gemm_qkv_kernel<<<gqkv, gblk, GEMM_SMEM_BYTES>>>(xhp, wtp, bq, bk, bv, qp, kp, vp);

    dim3 agrid(NCHUNK, NHEAD, BATCH);
    attn_kernel<<<agrid, gblk, ATTN_SMEM_BYTES>>>(mask);

    dim3 go(HIDDEN / 128, MROWS / 128);            // 8 x 64
    gemm_o_kernel<<<go, gblk, GEMM_SMEM_BYTES>>>(cp, wt_o, bo, out);
}

// round 12
// speedup vs baseline: 2.5470x; 1.0380x over previous
#include <cuda_runtime.h>
#include <cuda_fp16.h>
#include <cstdint>

// ---------------------------------------------------------------------------
// LongformerAttention  B=2, S=4096, HID=1024, H=16, D=64, W=64
// Round 12: 1/8 scale folded into Wq (bit-exact), hoisted mask predicates,
// GEMM prefetch repositioned after first ks-step.
// ---------------------------------------------------------------------------

#define S_LEN   4096
#define HIDDEN  1024
#define NHEAD   16
#define HDIM    64
#define NCHUNK  64
#define BATCH   2
#define MROWS   (BATCH * S_LEN)   // 8192

__device__ __half g_Qh[(size_t)MROWS * HIDDEN];
__device__ __half g_Kh[(size_t)MROWS * HIDDEN];
__device__ __half g_Vh[(size_t)MROWS * HIDDEN];
__device__ __half g_ctxh[(size_t)MROWS * HIDDEN];
__device__ __half g_Xh[(size_t)MROWS * HIDDEN];
__device__ __half g_Wth[4][(size_t)HIDDEN * HIDDEN];     // fp16 TRANSPOSED W [n][k]

__device__ __forceinline__ void mma_f16(float c[4], const uint32_t a[4], const uint32_t b[2]) {
    asm volatile(
        "mma.sync.aligned.m16n8k16.row.col.f32.f16.f16.f32 "
        "{%0,%1,%2,%3}, {%4,%5,%6,%7}, {%8,%9}, {%0,%1,%2,%3};"
        : "+f"(c[0]), "+f"(c[1]), "+f"(c[2]), "+f"(c[3])
        : "r"(a[0]), "r"(a[1]), "r"(a[2]), "r"(a[3]), "r"(b[0]), "r"(b[1]));
}

__device__ __forceinline__ void cp_async16(uint32_t dst, const void* src) {
    asm volatile("cp.async.cg.shared.global [%0], [%1], 16;\n"
                 :: "r"(dst), "l"(src));
}

__device__ __forceinline__ void cp_async16z(uint32_t dst, const void* src, uint32_t n) {
    asm volatile("cp.async.cg.shared.global [%0], [%1], 16, %2;\n"
                 :: "r"(dst), "l"(src), "r"(n));
}

__device__ __forceinline__ void ldsm_x4(uint32_t r[4], uint32_t addr) {
    asm volatile("ldmatrix.sync.aligned.m8n8.x4.shared.b16 {%0,%1,%2,%3}, [%4];"
                 : "=r"(r[0]), "=r"(r[1]), "=r"(r[2]), "=r"(r[3]) : "r"(addr));
}

__device__ __forceinline__ void ldsm_x4_t(uint32_t r[4], uint32_t addr) {
    asm volatile("ldmatrix.sync.aligned.m8n8.x4.trans.shared.b16 {%0,%1,%2,%3}, [%4];"
                 : "=r"(r[0]), "=r"(r[1]), "=r"(r[2]), "=r"(r[3]) : "r"(addr));
}

// ---------------------------------------------------------------------------
// Merged prepass: z=0..3 -> transpose+convert W[z] (z=0: Wq scaled by 1/8,
// power-of-two => bit-exact fp16 exponent shift); z=4,5 -> convert X half
// ---------------------------------------------------------------------------
__global__ __launch_bounds__(256) void prepass_kernel(
    const float* __restrict__ X,
    const float* __restrict__ w0, const float* __restrict__ w1,
    const float* __restrict__ w2, const float* __restrict__ w3,
    __half* __restrict__ Xh, __half* __restrict__ out4)
{
    const int z = blockIdx.z;
    if (z < 4) {
        __shared__ float tile[32][33];
        const float* in = (z == 0) ? w0 : (z == 1) ? w1 : (z == 2) ? w2 : w3;
        const float scale = (z == 0) ? 0.125f : 1.0f;
        __half* out = out4 + (size_t)z * HIDDEN * HIDDEN;
        int k0 = blockIdx.x * 32, n0 = blockIdx.y * 32;
        int tx = threadIdx.x & 31, ty = threadIdx.x >> 5;
#pragma unroll
        for (int i = 0; i < 32; i += 8)
            tile[ty + i][tx] = in[(size_t)(k0 + ty + i) * HIDDEN + n0 + tx];
        __syncthreads();
#pragma unroll
        for (int i = 0; i < 32; i += 8)
            out[(size_t)(n0 + ty + i) * HIDDEN + k0 + tx] =
                __float2half_rn(tile[tx][ty + i] * scale);
    } else {
        int blk = (z - 4) * 1024 + blockIdx.y * 32 + blockIdx.x;
#pragma unroll
        for (int i = 0; i < 4; i++) {
            int idx = (blk * 4 + i) * 256 + threadIdx.x;
            float4 v = ((const float4*)X)[idx];
            ((__half2*)Xh)[2 * idx]     = __floats2half2_rn(v.x, v.y);
            ((__half2*)Xh)[2 * idx + 1] = __floats2half2_rn(v.z, v.w);
        }
    }
}

// ---------------------------------------------------------------------------
// fp16 GEMM: C[M,N] = A[M,K] @ Bt[N,K]^T + bias[N]*bias_scale
// Block 128x128, BK=64, 3-stage cp.async, fully unrolled, prefetch after ks=0.
// ---------------------------------------------------------------------------
#define GK 1024
#define GN 1024
#define TSH 72
#define T_HALVES (128 * TSH)
#define STAGE_HALVES (2 * T_HALVES)
#define GEMM_SMEM_BYTES (3 * STAGE_HALVES * 2)  // 110592

template <bool OUT_HALF>
__device__ __forceinline__ void gemm_body_f16(
    const __half* __restrict__ A, const __half* __restrict__ Bt,
    const float* __restrict__ bias, float bias_scale,
    void* __restrict__ Cv, __half* sm)
{
    const int tid  = threadIdx.x;
    const int lane = tid & 31;
    const int wid  = tid >> 5;
    const int wm   = wid >> 2;
    const int wn   = wid & 3;
    const int qq   = lane >> 2;
    const int qk   = lane & 3;
    const int brow = blockIdx.y * 128;
    const int bcol = blockIdx.x * 128;

    const int g  = lane >> 3;
    const int lr = lane & 7;

    const uint32_t sm_u = (uint32_t)__cvta_generic_to_shared(sm);

    float acc[4][4][4];
#pragma unroll
    for (int i = 0; i < 4; i++)
#pragma unroll
        for (int j = 0; j < 4; j++)
#pragma unroll
            for (int t = 0; t < 4; t++) acc[i][j][t] = 0.f;

    const int ld_r = tid >> 3;
    const int ld_c = tid & 7;
    const __half* Ag = A + (size_t)(brow + ld_r) * GK + ld_c * 8;
    const __half* Bg = Bt + (size_t)(bcol + ld_r) * GK + ld_c * 8;
    const uint32_t st_off = (uint32_t)(ld_r * 144 + ld_c * 16);

    auto issue = [&](int slot, int k0) {
        uint32_t as_u = sm_u + (uint32_t)(slot * STAGE_HALVES) * 2u + st_off;
        uint32_t bs_u = as_u + (uint32_t)T_HALVES * 2u;
#pragma unroll
        for (int i = 0; i < 4; i++)
            cp_async16(as_u + (uint32_t)(i * 32 * 144), Ag + (size_t)(i * 32) * GK + k0);
#pragma unroll
        for (int i = 0; i < 4; i++)
            cp_async16(bs_u + (uint32_t)(i * 32 * 144), Bg + (size_t)(i * 32) * GK + k0);
        asm volatile("cp.async.commit_group;\n" ::: "memory");
    };

    issue(0, 0);
    issue(1, 64);

    const uint32_t a_off = (uint32_t)((wm * 64 + (lane & 15)) * 144 + (lane >> 4) * 16);
    const uint32_t b_off = (uint32_t)T_HALVES * 2u +
                           (uint32_t)((wn * 32 + (g >> 1) * 8 + lr) * 144 + (g & 1) * 16);

#pragma unroll
    for (int t = 0; t < 16; t++) {
        if (t == 15)
            asm volatile("cp.async.wait_group 0;\n" ::: "memory");
        else
            asm volatile("cp.async.wait_group 1;\n" ::: "memory");
        __syncthreads();

        const uint32_t base = sm_u + (uint32_t)((t % 3) * STAGE_HALVES) * 2u;
        const uint32_t a_base = base + a_off;
        const uint32_t b_base = base + b_off;

#pragma unroll
        for (int ks = 0; ks < 4; ks++) {
            const uint32_t kboff = (uint32_t)(ks * 32);
            uint32_t af[4][4];
#pragma unroll
            for (int mt = 0; mt < 4; mt++)
                ldsm_x4(af[mt], a_base + (uint32_t)(mt * 16 * 144) + kboff);
            uint32_t bf[2][4];
#pragma unroll
            for (int ntp = 0; ntp < 2; ntp++)
                ldsm_x4(bf[ntp], b_base + (uint32_t)(ntp * 16 * 144) + kboff);
#pragma unroll
            for (int mt = 0; mt < 4; mt++)
#pragma unroll
                for (int nt = 0; nt < 4; nt++)
                    mma_f16(acc[mt][nt], af[mt], &bf[nt >> 1][(nt & 1) * 2]);

            // prefetch after the first ks-step: LSU free for critical LDSM at
            // barrier exit; still ~3/4 iteration of slack for the cp.async.
            if (ks == 0 && t + 2 < 16)
                issue((t + 2) % 3, (t + 2) * 64);
        }
    }

#pragma unroll
    for (int nt = 0; nt < 4; nt++) {
        int cc = bcol + wn * 32 + nt * 8 + 2 * qk;
        float2 bv = *(const float2*)(bias + cc);
        bv.x *= bias_scale; bv.y *= bias_scale;
#pragma unroll
        for (int mt = 0; mt < 4; mt++) {
            int r = brow + wm * 64 + mt * 16 + qq;
            if (OUT_HALF) {
                __half* C = (__half*)Cv;
                *(__half2*)(C + (size_t)r * GN + cc) =
                    __floats2half2_rn(acc[mt][nt][0] + bv.x, acc[mt][nt][1] + bv.y);
                *(__half2*)(C + (size_t)(r + 8) * GN + cc) =
                    __floats2half2_rn(acc[mt][nt][2] + bv.x, acc[mt][nt][3] + bv.y);
            } else {
                float* C = (float*)Cv;
                *(float2*)(C + (size_t)r * GN + cc) =
                    make_float2(acc[mt][nt][0] + bv.x, acc[mt][nt][1] + bv.y);
                *(float2*)(C + (size_t)(r + 8) * GN + cc) =
                    make_float2(acc[mt][nt][2] + bv.x, acc[mt][nt][3] + bv.y);
            }
        }
    }
}

__global__ __launch_bounds__(256, 2) void gemm_qkv_kernel(
    const __half* __restrict__ X, const __half* __restrict__ Wt4,
    const float* __restrict__ bq, const float* __restrict__ bk,
    const float* __restrict__ bv,
    __half* __restrict__ Q, __half* __restrict__ K, __half* __restrict__ V)
{
    extern __shared__ __half smh[];
    const __half* W = Wt4 + (size_t)blockIdx.z * HIDDEN * HIDDEN;
    const float* b  = (blockIdx.z == 0) ? bq : (blockIdx.z == 1) ? bk : bv;
    const float bs  = (blockIdx.z == 0) ? 0.125f : 1.0f;   // match Wq scale fold
    __half*      C  = (blockIdx.z == 0) ? Q  : (blockIdx.z == 1) ? K  : V;
    gemm_body_f16<true>(X, W, b, bs, C, smh);
}

__global__ __launch_bounds__(256, 2) void gemm_o_kernel(
    const __half* __restrict__ A, const __half* __restrict__ W,
    const float* __restrict__ b, float* __restrict__ C)
{
    extern __shared__ __half smh[];
    gemm_body_f16<false>(A, W, b, 1.0f, C, smh);
}

// ---------------------------------------------------------------------------
// Banded attention: scores arrive pre-scaled (Wq fold). Hoisted mask preds.
// ---------------------------------------------------------------------------
#define QS_OFF    0
#define KS_OFF    4608
#define VS_OFF    18432
#define PH_OFF    0
#define PH_STRIDE 200
#define MISC_HALF 32256
#define ATTN_SMEM_BYTES (MISC_HALF * 2 + 704 * 4)   // 67328

__global__ __launch_bounds__(256) void attn_kernel(const float* __restrict__ maskp)
{
    extern __shared__ __half smh[];
    __half* Ph = smh + PH_OFF;
    float* vld  = (float*)(smh + MISC_HALF);
    float* redM = vld + 192;
    float* redS = redM + 256;

    const int c = blockIdx.x;
    const int h = blockIdx.y;
    const int b = blockIdx.z;
    const int tid  = threadIdx.x;
    const int lane = tid & 31;
    const int wid  = tid >> 5;
    const int wm   = wid >> 2;
    const int wn   = wid & 3;
    const int qq   = lane >> 2;
    const int qk   = lane & 3;
    const int g    = lane >> 3;
    const int lr   = lane & 7;

    const size_t headoff = (size_t)h * HDIM;
    const size_t bbase   = (size_t)b * S_LEN;
    const int base = c * 64 - 64;

    const uint32_t sm_u = (uint32_t)__cvta_generic_to_shared(smh);
    const uint32_t qs_u = sm_u + QS_OFF * 2;
    const uint32_t ks_u = sm_u + KS_OFF * 2;
    const uint32_t vs_u = sm_u + VS_OFF * 2;

#pragma unroll
    for (int it = 0; it < 2; it++) {
        int idx = tid + it * 256;
        int r = idx >> 3, cc = idx & 7;
        cp_async16(qs_u + (uint32_t)(r * 144 + cc * 16),
                   g_Qh + (bbase + c * 64 + r) * HIDDEN + headoff + cc * 8);
    }
#pragma unroll
    for (int it = 0; it < 6; it++) {
        int idx = tid + it * 256;
        int r = idx >> 3, cc = idx & 7;
        int jg = base + r;
        bool ok = (jg >= 0) && (jg < S_LEN);
        int jc = ok ? jg : 0;
        cp_async16z(ks_u + (uint32_t)(r * 144 + cc * 16),
                    g_Kh + (bbase + jc) * HIDDEN + headoff + cc * 8, ok ? 16u : 0u);
    }
    asm volatile("cp.async.commit_group;\n" ::: "memory");

#pragma unroll
    for (int it = 0; it < 6; it++) {
        int idx = tid + it * 256;
        int r = idx >> 3, cc = idx & 7;
        int jg = base + r;
        bool ok = (jg >= 0) && (jg < S_LEN);
        int jc = ok ? jg : 0;
        cp_async16z(vs_u + (uint32_t)(r * 144 + cc * 16),
                    g_Vh + (bbase + jc) * HIDDEN + headoff + cc * 8, ok ? 16u : 0u);
    }
    asm volatile("cp.async.commit_group;\n" ::: "memory");

    if (tid < 192) {
        int jg = base + tid;
        vld[tid] = (jg >= 0 && jg < S_LEN && maskp[b * S_LEN + jg] > 0.f) ? 1.f : 0.f;
    }

    asm volatile("cp.async.wait_group 1;\n" ::: "memory");
    __syncthreads();

    // ---- Phase A: S = Q K^T (pre-scaled by 1/8 via Wq fold)
    float acc[2][6][4];
#pragma unroll
    for (int mt = 0; mt < 2; mt++)
#pragma unroll
        for (int nt = 0; nt < 6; nt++)
#pragma unroll
            for (int t = 0; t < 4; t++) acc[mt][nt][t] = 0.f;

    {
        const uint32_t a_base = qs_u + (uint32_t)((wm * 32 + (lane & 15)) * 144 + (lane >> 4) * 16);
        const uint32_t b_base = ks_u + (uint32_t)((wn * 48 + (g >> 1) * 8 + lr) * 144 + (g & 1) * 16);
#pragma unroll
        for (int ks = 0; ks < 4; ks++) {
            const uint32_t kboff = (uint32_t)(ks * 32);
            uint32_t af[2][4];
#pragma unroll
            for (int mt = 0; mt < 2; mt++)
                ldsm_x4(af[mt], a_base + (uint32_t)(mt * 16 * 144) + kboff);
            uint32_t bf[3][4];
#pragma unroll
            for (int ntp = 0; ntp < 3; ntp++)
                ldsm_x4(bf[ntp], b_base + (uint32_t)(ntp * 16 * 144) + kboff);
#pragma unroll
            for (int mt = 0; mt < 2; mt++)
#pragma unroll
                for (int nt = 0; nt < 6; nt++)
                    mma_f16(acc[mt][nt], af[mt], &bf[nt >> 1][(nt & 1) * 2]);
        }
    }

    // ---- hoisted column validity (12 distinct cols per thread, loaded once)
    bool vb[6][2];
#pragma unroll
    for (int nt = 0; nt < 6; nt++)
#pragma unroll
        for (int e = 0; e < 2; e++)
            vb[nt][e] = vld[wn * 48 + nt * 8 + 2 * qk + e] > 0.f;

    // ---- band mask + row-max partials
    float mrow[2][2];
#pragma unroll
    for (int mt = 0; mt < 2; mt++)
#pragma unroll
        for (int hf = 0; hf < 2; hf++) mrow[mt][hf] = -1e30f;

#pragma unroll
    for (int mt = 0; mt < 2; mt++)
#pragma unroll
        for (int nt = 0; nt < 6; nt++) {
            int colb = wn * 48 + nt * 8 + 2 * qk;
#pragma unroll
            for (int hf = 0; hf < 2; hf++) {
                int row = wm * 32 + mt * 16 + qq + 8 * hf;
#pragma unroll
                for (int e = 0; e < 2; e++) {
                    int col = colb + e;
                    float v = acc[mt][nt][hf * 2 + e];
                    bool ok = (col >= row) && (col <= row + 128) && vb[nt][e];
                    v = ok ? v : -1e9f;
                    acc[mt][nt][hf * 2 + e] = v;
                    mrow[mt][hf] = fmaxf(mrow[mt][hf], v);
                }
            }
        }
#pragma unroll
    for (int mt = 0; mt < 2; mt++)
#pragma unroll
        for (int hf = 0; hf < 2; hf++) {
            float m = mrow[mt][hf];
            m = fmaxf(m, __shfl_xor_sync(0xffffffffu, m, 1));
            m = fmaxf(m, __shfl_xor_sync(0xffffffffu, m, 2));
            mrow[mt][hf] = m;
        }
    if (qk == 0) {
#pragma unroll
        for (int mt = 0; mt < 2; mt++)
#pragma unroll
            for (int hf = 0; hf < 2; hf++)
                redM[wn * 64 + wm * 32 + mt * 16 + qq + 8 * hf] = mrow[mt][hf];
    }
    __syncthreads();

    // ---- global max, exp, fp16 P store (overlay), row sums
    float gmv[2][2], srow[2][2];
#pragma unroll
    for (int mt = 0; mt < 2; mt++)
#pragma unroll
        for (int hf = 0; hf < 2; hf++) {
            int row = wm * 32 + mt * 16 + qq + 8 * hf;
            float m = fmaxf(fmaxf(redM[row], redM[64 + row]),
                            fmaxf(redM[128 + row], redM[192 + row]));
            gmv[mt][hf] = m;
            srow[mt][hf] = 0.f;
        }

#pragma unroll
    for (int mt = 0; mt < 2; mt++)
#pragma unroll
        for (int nt = 0; nt < 6; nt++) {
            int colb = wn * 48 + nt * 8 + 2 * qk;
#pragma unroll
            for (int hf = 0; hf < 2; hf++) {
                int row = wm * 32 + mt * 16 + qq + 8 * hf;
                float p0 = __expf(acc[mt][nt][hf * 2 + 0] - gmv[mt][hf]);
                float p1 = __expf(acc[mt][nt][hf * 2 + 1] - gmv[mt][hf]);
                __half h0 = __float2half_rn(p0);
                __half h1 = __float2half_rn(p1);
                srow[mt][hf] += __half2float(h0) + __half2float(h1);
                *(__half2*)(Ph + row * PH_STRIDE + colb) = __halves2half2(h0, h1);
            }
        }

#pragma unroll
    for (int mt = 0; mt < 2; mt++)
#pragma unroll
        for (int hf = 0; hf < 2; hf++) {
            float s = srow[mt][hf];
            s += __shfl_xor_sync(0xffffffffu, s, 1);
            s += __shfl_xor_sync(0xffffffffu, s, 2);
            srow[mt][hf] = s;
        }
    if (qk == 0) {
#pragma unroll
        for (int mt = 0; mt < 2; mt++)
#pragma unroll
            for (int hf = 0; hf < 2; hf++)
                redS[wn * 64 + wm * 32 + mt * 16 + qq + 8 * hf] = srow[mt][hf];
    }

    asm volatile("cp.async.wait_group 0;\n" ::: "memory");
    __syncthreads();

    // ---- Phase B: ctx = P V
    float c2[2][2][4];
#pragma unroll
    for (int mt = 0; mt < 2; mt++)
#pragma unroll
        for (int nt = 0; nt < 2; nt++)
#pragma unroll
            for (int t = 0; t < 4; t++) c2[mt][nt][t] = 0.f;

    {
        const uint32_t a_base = sm_u + (uint32_t)(PH_OFF * 2 +
                                (wm * 32 + (lane & 15)) * (PH_STRIDE * 2) + (lane >> 4) * 16);
        const uint32_t bt_base = vs_u + (uint32_t)(((g & 1) * 8 + lr) * 144 +
                                 (wn * 16 + (g >> 1) * 8) * 2);
#pragma unroll
        for (int ks = 0; ks < 12; ks++) {
            uint32_t af[2][4];
#pragma unroll
            for (int mt = 0; mt < 2; mt++)
                ldsm_x4(af[mt], a_base + (uint32_t)(mt * 16 * PH_STRIDE * 2 + ks * 32));
            uint32_t bf[4];
            ldsm_x4_t(bf, bt_base + (uint32_t)(ks * 16 * 144));
#pragma unroll
            for (int mt = 0; mt < 2; mt++)
#pragma unroll
                for (int nt = 0; nt < 2; nt++)
                    mma_f16(c2[mt][nt], af[mt], &bf[nt * 2]);
        }
    }

    // ---- epilogue
#pragma unroll
    for (int mt = 0; mt < 2; mt++)
#pragma unroll
        for (int hf = 0; hf < 2; hf++) {
            int row = wm * 32 + mt * 16 + qq + 8 * hf;
            float s = redS[row] + redS[64 + row] + redS[128 + row] + redS[192 + row];
            float rinv = 1.f / s;
            __half* Og = g_ctxh + (bbase + c * 64 + row) * HIDDEN + headoff;
#pragma unroll
            for (int nt = 0; nt < 2; nt++) {
                int col = wn * 16 + nt * 8 + 2 * qk;
                *(__half2*)(Og + col) = __floats2half2_rn(c2[mt][nt][hf * 2 + 0] * rinv,
                                                          c2[mt][nt][hf * 2 + 1] * rinv);
            }
        }
}

// ---------------------------------------------------------------------------
extern "C" void kernel_launch(void* const* d_in, const int* in_sizes, int n_in,
                              void* d_out, int out_size)
{
    const float* X    = (const float*)d_in[0];
    const float* mask = (const float*)d_in[1];
    const float* Wq   = (const float*)d_in[2];
    const float* bq   = (const float*)d_in[3];
    const float* Wk   = (const float*)d_in[4];
    const float* bk   = (const float*)d_in[5];
    const float* Wv   = (const float*)d_in[6];
    const float* bv   = (const float*)d_in[7];
    const float* Wo   = (const float*)d_in[8];
    const float* bo   = (const float*)d_in[9];
    float* out = (float*)d_out;

    __half *qp, *kp, *vp, *cp, *xhp, *wtp;
    cudaGetSymbolAddress((void**)&qp, g_Qh);
    cudaGetSymbolAddress((void**)&kp, g_Kh);
    cudaGetSymbolAddress((void**)&vp, g_Vh);
    cudaGetSymbolAddress((void**)&cp, g_ctxh);
    cudaGetSymbolAddress((void**)&xhp, g_Xh);
    cudaGetSymbolAddress((void**)&wtp, g_Wth);
    __half* wt_o = wtp + 3 * (size_t)HIDDEN * HIDDEN;

    cudaFuncSetAttribute(attn_kernel, cudaFuncAttributeMaxDynamicSharedMemorySize,
                         ATTN_SMEM_BYTES);
    cudaFuncSetAttribute(gemm_qkv_kernel, cudaFuncAttributeMaxDynamicSharedMemorySize,
                         GEMM_SMEM_BYTES);
    cudaFuncSetAttribute(gemm_o_kernel, cudaFuncAttributeMaxDynamicSharedMemorySize,
                         GEMM_SMEM_BYTES);

    dim3 pgrid(32, 32, 6);
    prepass_kernel<<<pgrid, 256>>>(X, Wq, Wk, Wv, Wo, xhp, wtp);

    dim3 gblk(256);
    dim3 gqkv(HIDDEN / 128, MROWS / 128, 3);       // 8 x 64 x 3
    gemm_qkv_kernel<<<gqkv, gblk, GEMM_SMEM_BYTES>>>(xhp, wtp, bq, bk, bv, qp, kp, vp);

    dim3 agrid(NCHUNK, NHEAD, BATCH);
    attn_kernel<<<agrid, gblk, ATTN_SMEM_BYTES>>>(mask);

    dim3 go(HIDDEN / 128, MROWS / 128);            // 8 x 64
    gemm_o_kernel<<<go, gblk, GEMM_SMEM_BYTES>>>(cp, wt_o, bo, out);
}